// round 1
// baseline (speedup 1.0000x reference)
#include <cuda_runtime.h>
#include <math.h>

// Problem constants
#define T_STEPS 1024
#define BATCH   16
#define DIMK    1024
#define HEADS   8
#define NDIM    64
#define HN      512                 // HEADS*NDIM
#define ROWS    (T_STEPS*BATCH)     // 16384
#define OUT_MAIN ((size_t)T_STEPS*BATCH*HN)        // 8388608
#define SFIN_ELEMS ((size_t)BATCH*HEADS*NDIM*NDIM) // 524288

// Scratch for the 4 projections (k,v,q,beta_pre): 4 * 16384 * 512 floats = 128 MB
__device__ float g_proj[4ull * ROWS * HN];

// ---------------------------------------------------------------------------
// Projection GEMM: C[m,n] = sum_k x[m,k] * W[n,k]
// x: [ROWS, DIMK] row-major. W: [HN, DIMK] row-major (so we compute x @ W^T).
// Tiles: BM=128, BN=128, BK=16, 256 threads, 8x8 per thread.
// grid = (HN/BN, ROWS/BM, 4)  -> z selects which W / which proj slab.
// ---------------------------------------------------------------------------
#define BM 128
#define BN 128
#define BK 16

__global__ __launch_bounds__(256, 2) void proj_gemm(
    const float* __restrict__ x,
    const float* __restrict__ Wk, const float* __restrict__ Wv,
    const float* __restrict__ Wq, const float* __restrict__ Wb)
{
    const int z = blockIdx.z;
    const float* __restrict__ W = (z == 0) ? Wk : (z == 1) ? Wv : (z == 2) ? Wq : Wb;
    float* __restrict__ C = g_proj + (size_t)z * ROWS * HN;

    __shared__ float As[BK][BM + 4];   // stride 132 floats = 528B (16B aligned rows)
    __shared__ float Bs[BK][BN + 4];

    const int tid = threadIdx.x;
    const int m0 = blockIdx.y * BM;
    const int n0 = blockIdx.x * BN;

    const int tx = tid & 15;           // 16 col groups of 8
    const int ty = tid >> 4;           // 16 row groups of 8

    const int lr = tid >> 2;           // 0..63  (load row within tile)
    const int lc = (tid & 3) * 4;      // 0,4,8,12 (k offset, float4)

    float acc[8][8];
#pragma unroll
    for (int i = 0; i < 8; ++i)
#pragma unroll
        for (int j = 0; j < 8; ++j) acc[i][j] = 0.f;

    const float* xA0 = x + (size_t)(m0 + lr) * DIMK + lc;
    const float* xA1 = x + (size_t)(m0 + lr + 64) * DIMK + lc;
    const float* wB0 = W + (size_t)(n0 + lr) * DIMK + lc;
    const float* wB1 = W + (size_t)(n0 + lr + 64) * DIMK + lc;

    for (int k0 = 0; k0 < DIMK; k0 += BK) {
        float4 a0 = *(const float4*)(xA0 + k0);
        float4 a1 = *(const float4*)(xA1 + k0);
        float4 b0 = *(const float4*)(wB0 + k0);
        float4 b1 = *(const float4*)(wB1 + k0);

        As[lc + 0][lr] = a0.x;  As[lc + 1][lr] = a0.y;
        As[lc + 2][lr] = a0.z;  As[lc + 3][lr] = a0.w;
        As[lc + 0][lr + 64] = a1.x;  As[lc + 1][lr + 64] = a1.y;
        As[lc + 2][lr + 64] = a1.z;  As[lc + 3][lr + 64] = a1.w;

        Bs[lc + 0][lr] = b0.x;  Bs[lc + 1][lr] = b0.y;
        Bs[lc + 2][lr] = b0.z;  Bs[lc + 3][lr] = b0.w;
        Bs[lc + 0][lr + 64] = b1.x;  Bs[lc + 1][lr + 64] = b1.y;
        Bs[lc + 2][lr + 64] = b1.z;  Bs[lc + 3][lr + 64] = b1.w;

        __syncthreads();

#pragma unroll
        for (int kk = 0; kk < BK; ++kk) {
            float4 av0 = *(const float4*)&As[kk][ty * 8];
            float4 av1 = *(const float4*)&As[kk][ty * 8 + 4];
            float4 bv0 = *(const float4*)&Bs[kk][tx * 8];
            float4 bv1 = *(const float4*)&Bs[kk][tx * 8 + 4];
            float a[8] = {av0.x, av0.y, av0.z, av0.w, av1.x, av1.y, av1.z, av1.w};
            float b[8] = {bv0.x, bv0.y, bv0.z, bv0.w, bv1.x, bv1.y, bv1.z, bv1.w};
#pragma unroll
            for (int i = 0; i < 8; ++i)
#pragma unroll
                for (int j = 0; j < 8; ++j)
                    acc[i][j] = fmaf(a[i], b[j], acc[i][j]);
        }
        __syncthreads();
    }

#pragma unroll
    for (int i = 0; i < 8; ++i) {
        float* cp = C + (size_t)(m0 + ty * 8 + i) * HN + n0 + tx * 8;
        *(float4*)cp       = make_float4(acc[i][0], acc[i][1], acc[i][2], acc[i][3]);
        *(float4*)(cp + 4) = make_float4(acc[i][4], acc[i][5], acc[i][6], acc[i][7]);
    }
}

// ---------------------------------------------------------------------------
// Sequential scan: one CTA per (b,h) chain. 512 threads.
// Thread t owns row i = t>>3, cols jb..jb+7 with jb = (t&7)*8 of the 64x64 state.
// ---------------------------------------------------------------------------
__device__ __forceinline__ float sigmoidf_acc(float v) {
    return 1.f / (1.f + expf(-v));
}

__global__ __launch_bounds__(512, 1) void scan_kernel(
    const float* __restrict__ S0,
    const float* __restrict__ b_beta,
    float* __restrict__ out,
    float* __restrict__ Sfin)     // may be null
{
    const int bh  = blockIdx.x;         // = b*HEADS + h
    const int b   = bh / HEADS;
    const int h   = bh % HEADS;
    const int tid = threadIdx.x;
    const int i   = tid >> 3;           // state row  0..63
    const int jb  = (tid & 7) * 8;      // state col base

    // Load initial state
    float S[8];
    const float* S0p = S0 + (size_t)bh * NDIM * NDIM + i * NDIM + jb;
#pragma unroll
    for (int e = 0; e < 8; ++e) S[e] = S0p[e];

    __shared__ float sv[4][NDIM];       // k, v, q, beta(sigmoided)

    const float* bb = b_beta + h * NDIM;
    const size_t slab = (size_t)ROWS * HN;
    const float* pk = g_proj + 0 * slab;
    const float* pv = g_proj + 1 * slab;
    const float* pq = g_proj + 2 * slab;
    const float* pbeta = g_proj + 3 * slab;

    const int lane = tid & 31;

    for (int t = 0; t < T_STEPS; ++t) {
        const size_t base = (size_t)(t * BATCH + b) * HN + h * NDIM;

        if (tid < 256) {
            const int p = tid >> 6;
            const int j = tid & 63;
            float val;
            if (p == 0)      val = pk[base + j];
            else if (p == 1) val = pv[base + j];
            else if (p == 2) val = pq[base + j];
            else             val = sigmoidf_acc(pbeta[base + j] + bb[j]);
            sv[p][j] = val;
        }
        __syncthreads();

        // inverse k-norm, computed redundantly per warp (no extra barrier)
        float ka = sv[0][lane];
        float kb2 = sv[0][lane + 32];
        float ss = ka * ka + kb2 * kb2;
#pragma unroll
        for (int o = 16; o > 0; o >>= 1) ss += __shfl_xor_sync(0xffffffffu, ss, o);
        const float inv = 1.f / (sqrtf(ss) + 1e-6f);

        float4 k4a = *(const float4*)&sv[0][jb];
        float4 k4b = *(const float4*)&sv[0][jb + 4];
        float kn[8] = {k4a.x * inv, k4a.y * inv, k4a.z * inv, k4a.w * inv,
                       k4b.x * inv, k4b.y * inv, k4b.z * inv, k4b.w * inv};

        // retrieved_i = sum_j S[i,j] * kn[j]  (8-lane row reduce)
        float r = 0.f;
#pragma unroll
        for (int e = 0; e < 8; ++e) r = fmaf(S[e], kn[e], r);
        r += __shfl_xor_sync(0xffffffffu, r, 1);
        r += __shfl_xor_sync(0xffffffffu, r, 2);
        r += __shfl_xor_sync(0xffffffffu, r, 4);

        const float delta = sv[1][i] - r;
        const float beta  = sv[3][i];

        float4 q4a = *(const float4*)&sv[2][jb];
        float4 q4b = *(const float4*)&sv[2][jb + 4];
        float qn[8] = {q4a.x, q4a.y, q4a.z, q4a.w, q4b.x, q4b.y, q4b.z, q4b.w};

        // S = tanh(beta*S + delta*kn);  Sq_i = sum_j S[i,j]*q[j]
        float acc = 0.f;
#pragma unroll
        for (int e = 0; e < 8; ++e) {
            float s = tanhf(fmaf(delta, kn[e], beta * S[e]));
            S[e] = s;
            acc = fmaf(s, qn[e], acc);
        }
        acc += __shfl_xor_sync(0xffffffffu, acc, 1);
        acc += __shfl_xor_sync(0xffffffffu, acc, 2);
        acc += __shfl_xor_sync(0xffffffffu, acc, 4);

        if ((tid & 7) == 0) {
            const float sg = sigmoidf_acc(acc);
            out[(size_t)t * BATCH * HN + b * HN + h * NDIM + i] = acc * acc * sg;
        }
        __syncthreads();   // protect sv before next step's loads
    }

    if (Sfin != nullptr) {
        float* sp = Sfin + (size_t)bh * NDIM * NDIM + i * NDIM + jb;
#pragma unroll
        for (int e = 0; e < 8; ++e) sp[e] = S[e];
    }
}

// ---------------------------------------------------------------------------
// Inputs (metadata order): x, S0, W_k, W_v, W_q, W_beta, b_beta
// Output: concat(output [T,B,H*N], S_final [B,H,N,N]) — S_final only if
// out_size covers it.
// ---------------------------------------------------------------------------
extern "C" void kernel_launch(void* const* d_in, const int* in_sizes, int n_in,
                              void* d_out, int out_size)
{
    const float* x   = (const float*)d_in[0];
    const float* S0  = (const float*)d_in[1];
    const float* Wk  = (const float*)d_in[2];
    const float* Wv  = (const float*)d_in[3];
    const float* Wq  = (const float*)d_in[4];
    const float* Wb  = (const float*)d_in[5];
    const float* bbt = (const float*)d_in[6];
    float* out = (float*)d_out;

    dim3 gg(HN / BN, ROWS / BM, 4);
    proj_gemm<<<gg, 256>>>(x, Wk, Wv, Wq, Wb);

    float* sfin = nullptr;
    if ((size_t)out_size >= OUT_MAIN + SFIN_ELEMS) sfin = out + OUT_MAIN;

    scan_kernel<<<BATCH * HEADS, 512>>>(S0, bbt, out, sfin);
}

// round 3
// speedup vs baseline: 1.4984x; 1.4984x over previous
#include <cuda_runtime.h>
#include <math.h>

// Problem constants
#define T_STEPS 1024
#define BATCH   16
#define DIMK    1024
#define HEADS   8
#define NDIM    64
#define HN      512                 // HEADS*NDIM
#define ROWS    (T_STEPS*BATCH)     // 16384
#define OUT_MAIN ((size_t)T_STEPS*BATCH*HN)        // 8388608
#define SFIN_ELEMS ((size_t)BATCH*HEADS*NDIM*NDIM) // 524288

// Scratch for the 4 projections (k,v,q,beta_sigmoided): 128 MB
__device__ float g_proj[4ull * ROWS * HN];

__device__ __forceinline__ float sigmoidf_acc(float v) {
    return 1.f / (1.f + expf(-v));
}

// ---------------------------------------------------------------------------
// tf32 helpers: 3xTF32 split GEMM (hi*hi + hi*lo + lo*hi) ~ fp32 accuracy
// ---------------------------------------------------------------------------
__device__ __forceinline__ void split_tf32(float x, unsigned& hi, unsigned& lo) {
    asm("cvt.rna.tf32.f32 %0, %1;" : "=r"(hi) : "f"(x));
    float l = x - __uint_as_float(hi);
    asm("cvt.rna.tf32.f32 %0, %1;" : "=r"(lo) : "f"(l));
}

__device__ __forceinline__ void mma_tf32(float c[4], const unsigned a[4], const unsigned b[2]) {
    asm volatile(
        "mma.sync.aligned.m16n8k8.row.col.f32.tf32.tf32.f32 "
        "{%0,%1,%2,%3},{%4,%5,%6,%7},{%8,%9},{%0,%1,%2,%3};"
        : "+f"(c[0]), "+f"(c[1]), "+f"(c[2]), "+f"(c[3])
        : "r"(a[0]), "r"(a[1]), "r"(a[2]), "r"(a[3]), "r"(b[0]), "r"(b[1]));
}

// ---------------------------------------------------------------------------
// Projection GEMM (tensor cores): C[m,n] = sum_k x[m,k] * W[n,k]
// CTA tile 128x128, BK=16, 128 threads (4 warps), warp tile 64x64.
// grid = (HN/128, ROWS/128, 4). z==3 applies sigmoid(+b_beta) in epilogue.
// ---------------------------------------------------------------------------
#define GBM 128
#define GBN 128
#define GBK 16
#define SMS (GBM + 8)   // smem row stride (floats): banks (8k+m) conflict-free frags

__global__ __launch_bounds__(128, 2) void proj_gemm_tc(
    const float* __restrict__ x,
    const float* __restrict__ Wk, const float* __restrict__ Wv,
    const float* __restrict__ Wq, const float* __restrict__ Wb,
    const float* __restrict__ b_beta)
{
    const int z = blockIdx.z;
    const float* __restrict__ W = (z == 0) ? Wk : (z == 1) ? Wv : (z == 2) ? Wq : Wb;
    float* __restrict__ C = g_proj + (size_t)z * ROWS * HN;

    __shared__ float As[2][GBK][SMS];
    __shared__ float Bs[2][GBK][SMS];

    const int tid  = threadIdx.x;
    const int lane = tid & 31;
    const int wid  = tid >> 5;
    const int wm   = wid >> 1;        // 0..1
    const int wn   = wid & 1;         // 0..1
    const int g    = lane >> 2;       // 0..7
    const int tig  = lane & 3;        // 0..3

    const int m0 = blockIdx.y * GBM;
    const int n0 = blockIdx.x * GBN;

    // Global load mapping: thread loads 4 float4 for A and 4 for B per chunk.
    const int lm = tid >> 2;          // 0..31, +32*i
    const int lk = (tid & 3) * 4;     // 0,4,8,12
    const float* xA = x + (size_t)(m0 + lm) * DIMK + lk;
    const float* wB = W + (size_t)(n0 + lm) * DIMK + lk;

    float c[4][8][4];
#pragma unroll
    for (int mi = 0; mi < 4; ++mi)
#pragma unroll
        for (int ni = 0; ni < 8; ++ni)
#pragma unroll
            for (int e = 0; e < 4; ++e) c[mi][ni][e] = 0.f;

    float4 ra[4], rb[4];
#pragma unroll
    for (int i2 = 0; i2 < 4; ++i2) {
        ra[i2] = *(const float4*)(xA + (size_t)i2 * 32 * DIMK);
        rb[i2] = *(const float4*)(wB + (size_t)i2 * 32 * DIMK);
    }
#pragma unroll
    for (int i2 = 0; i2 < 4; ++i2) {
        const float av[4] = {ra[i2].x, ra[i2].y, ra[i2].z, ra[i2].w};
        const float bv[4] = {rb[i2].x, rb[i2].y, rb[i2].z, rb[i2].w};
#pragma unroll
        for (int jj = 0; jj < 4; ++jj) {
            As[0][lk + jj][lm + i2 * 32] = av[jj];
            Bs[0][lk + jj][lm + i2 * 32] = bv[jj];
        }
    }
    __syncthreads();

    int buf = 0;
    for (int ch = 0; ch < DIMK / GBK; ++ch) {
        if (ch + 1 < DIMK / GBK) {
            const size_t koff = (size_t)(ch + 1) * GBK;
#pragma unroll
            for (int i2 = 0; i2 < 4; ++i2) {
                ra[i2] = *(const float4*)(xA + koff + (size_t)i2 * 32 * DIMK);
                rb[i2] = *(const float4*)(wB + koff + (size_t)i2 * 32 * DIMK);
            }
        }

#pragma unroll
        for (int kk = 0; kk < GBK; kk += 8) {
            unsigned bhi[8][2], blo[8][2];
#pragma unroll
            for (int ni = 0; ni < 8; ++ni) {
                const int ncol = wn * 64 + ni * 8 + g;
                float b0 = Bs[buf][kk + tig][ncol];
                float b1 = Bs[buf][kk + tig + 4][ncol];
                split_tf32(b0, bhi[ni][0], blo[ni][0]);
                split_tf32(b1, bhi[ni][1], blo[ni][1]);
            }
#pragma unroll
            for (int mi = 0; mi < 4; ++mi) {
                const int mrow = wm * 64 + mi * 16;
                unsigned ahi[4], alo[4];
                float a0 = As[buf][kk + tig][mrow + g];
                float a1 = As[buf][kk + tig][mrow + g + 8];
                float a2 = As[buf][kk + tig + 4][mrow + g];
                float a3 = As[buf][kk + tig + 4][mrow + g + 8];
                split_tf32(a0, ahi[0], alo[0]);
                split_tf32(a1, ahi[1], alo[1]);
                split_tf32(a2, ahi[2], alo[2]);
                split_tf32(a3, ahi[3], alo[3]);
#pragma unroll
                for (int ni = 0; ni < 8; ++ni) {
                    mma_tf32(c[mi][ni], ahi, bhi[ni]);
                    mma_tf32(c[mi][ni], ahi, blo[ni]);
                    mma_tf32(c[mi][ni], alo, bhi[ni]);
                }
            }
        }

        if (ch + 1 < DIMK / GBK) {
#pragma unroll
            for (int i2 = 0; i2 < 4; ++i2) {
                const float av[4] = {ra[i2].x, ra[i2].y, ra[i2].z, ra[i2].w};
                const float bv[4] = {rb[i2].x, rb[i2].y, rb[i2].z, rb[i2].w};
#pragma unroll
                for (int jj = 0; jj < 4; ++jj) {
                    As[buf ^ 1][lk + jj][lm + i2 * 32] = av[jj];
                    Bs[buf ^ 1][lk + jj][lm + i2 * 32] = bv[jj];
                }
            }
            __syncthreads();
            buf ^= 1;
        }
    }

    // Epilogue: z==3 applies sigmoid(c + b_beta[col]) so the scan reads beta directly.
#pragma unroll
    for (int mi = 0; mi < 4; ++mi) {
        const int r0 = m0 + wm * 64 + mi * 16 + g;
#pragma unroll
        for (int ni = 0; ni < 8; ++ni) {
            const int col = n0 + wn * 64 + ni * 8 + 2 * tig;
            float v0 = c[mi][ni][0], v1 = c[mi][ni][1];
            float v2 = c[mi][ni][2], v3 = c[mi][ni][3];
            if (z == 3) {
                const float bb0 = b_beta[col], bb1 = b_beta[col + 1];
                v0 = sigmoidf_acc(v0 + bb0);
                v1 = sigmoidf_acc(v1 + bb1);
                v2 = sigmoidf_acc(v2 + bb0);
                v3 = sigmoidf_acc(v3 + bb1);
            }
            float2* p0 = (float2*)&C[(size_t)r0 * HN + col];
            float2* p1 = (float2*)&C[(size_t)(r0 + 8) * HN + col];
            *p0 = make_float2(v0, v1);
            *p1 = make_float2(v2, v3);
        }
    }
}

// ---------------------------------------------------------------------------
// Sequential scan: one CTA per (b,h). 512 threads; thread owns S row i=tid>>3,
// cols jb..jb+7. Double-buffered k/v/q/beta staging -> 1 barrier per step,
// t+1 load issued before compute (latency hidden under tanh chain).
// ---------------------------------------------------------------------------
__global__ __launch_bounds__(512, 1) void scan_kernel(
    const float* __restrict__ S0,
    float* __restrict__ out,
    float* __restrict__ Sfin)
{
    const int bh  = blockIdx.x;
    const int b   = bh >> 3;
    const int h   = bh & 7;
    const int tid = threadIdx.x;
    const int i   = tid >> 3;
    const int jb  = (tid & 7) * 8;

    float S[8];
    const float* S0p = S0 + (size_t)bh * NDIM * NDIM + i * NDIM + jb;
#pragma unroll
    for (int e = 0; e < 8; ++e) S[e] = S0p[e];

    __shared__ float sv[2][4][NDIM];

    const int p = tid >> 6;        // 0..3 selects k/v/q/beta (tid<256)
    const int j = tid & 63;
    const float* myp = g_proj + (size_t)p * ((size_t)ROWS * HN) + b * HN + h * NDIM + j;

    if (tid < 256) sv[0][p][j] = myp[0];
    __syncthreads();

    float* outp = out + (size_t)b * HN + h * NDIM + i;

    for (int t = 0; t < T_STEPS; ++t) {
        float pre = 0.f;
        const bool do_pre = (tid < 256) && (t + 1 < T_STEPS);
        if (do_pre) pre = __ldg(myp + (size_t)(t + 1) * (BATCH * HN));

        const float (*cur)[NDIM] = sv[t & 1];

        float4 k4a = *(const float4*)&cur[0][jb];
        float4 k4b = *(const float4*)&cur[0][jb + 4];

        // ||k||^2: each thread sums its 8 cols, reduce over the 8-lane row group
        float ss = k4a.x * k4a.x + k4a.y * k4a.y + k4a.z * k4a.z + k4a.w * k4a.w
                 + k4b.x * k4b.x + k4b.y * k4b.y + k4b.z * k4b.z + k4b.w * k4b.w;
        ss += __shfl_xor_sync(0xffffffffu, ss, 1);
        ss += __shfl_xor_sync(0xffffffffu, ss, 2);
        ss += __shfl_xor_sync(0xffffffffu, ss, 4);
        const float inv = 1.f / (sqrtf(ss) + 1e-6f);

        float kn[8] = {k4a.x * inv, k4a.y * inv, k4a.z * inv, k4a.w * inv,
                       k4b.x * inv, k4b.y * inv, k4b.z * inv, k4b.w * inv};

        float r = 0.f;
#pragma unroll
        for (int e = 0; e < 8; ++e) r = fmaf(S[e], kn[e], r);
        r += __shfl_xor_sync(0xffffffffu, r, 1);
        r += __shfl_xor_sync(0xffffffffu, r, 2);
        r += __shfl_xor_sync(0xffffffffu, r, 4);

        const float delta = cur[1][i] - r;
        const float beta  = cur[3][i];     // pre-sigmoided in GEMM epilogue

        float4 q4a = *(const float4*)&cur[2][jb];
        float4 q4b = *(const float4*)&cur[2][jb + 4];
        const float qn[8] = {q4a.x, q4a.y, q4a.z, q4a.w, q4b.x, q4b.y, q4b.z, q4b.w};

        float acc = 0.f;
#pragma unroll
        for (int e = 0; e < 8; ++e) {
            float s = tanhf(fmaf(delta, kn[e], beta * S[e]));
            S[e] = s;
            acc = fmaf(s, qn[e], acc);
        }
        acc += __shfl_xor_sync(0xffffffffu, acc, 1);
        acc += __shfl_xor_sync(0xffffffffu, acc, 2);
        acc += __shfl_xor_sync(0xffffffffu, acc, 4);

        if ((tid & 7) == 0) {
            const float sg = sigmoidf_acc(acc);
            outp[(size_t)t * (BATCH * HN)] = acc * acc * sg;
        }

        if (do_pre) sv[(t + 1) & 1][p][j] = pre;
        __syncthreads();
    }

    if (Sfin != nullptr) {
        float* sp = Sfin + (size_t)bh * NDIM * NDIM + i * NDIM + jb;
#pragma unroll
        for (int e = 0; e < 8; ++e) sp[e] = S[e];
    }
}

// ---------------------------------------------------------------------------
// Inputs: x, S0, W_k, W_v, W_q, W_beta, b_beta
// ---------------------------------------------------------------------------
extern "C" void kernel_launch(void* const* d_in, const int* in_sizes, int n_in,
                              void* d_out, int out_size)
{
    const float* x   = (const float*)d_in[0];
    const float* S0  = (const float*)d_in[1];
    const float* Wk  = (const float*)d_in[2];
    const float* Wv  = (const float*)d_in[3];
    const float* Wq  = (const float*)d_in[4];
    const float* Wb  = (const float*)d_in[5];
    const float* bbt = (const float*)d_in[6];
    float* out = (float*)d_out;

    dim3 gg(HN / GBN, ROWS / GBM, 4);
    proj_gemm_tc<<<gg, 128>>>(x, Wk, Wv, Wq, Wb, bbt);

    float* sfin = nullptr;
    if ((size_t)out_size >= OUT_MAIN + SFIN_ELEMS) sfin = out + OUT_MAIN;

    scan_kernel<<<BATCH * HEADS, 512>>>(S0, out, sfin);
}

// round 4
// speedup vs baseline: 1.5142x; 1.0105x over previous
#include <cuda_runtime.h>
#include <math.h>

// Problem constants
#define T_STEPS 1024
#define BATCH   16
#define DIMK    1024
#define HEADS   8
#define NDIM    64
#define HN      512                 // HEADS*NDIM
#define ROWS    (T_STEPS*BATCH)     // 16384
#define OUT_MAIN ((size_t)T_STEPS*BATCH*HN)        // 8388608
#define SFIN_ELEMS ((size_t)BATCH*HEADS*NDIM*NDIM) // 524288

// Scratch for the 4 projections (k,v,q,beta_sigmoided): 128 MB
__device__ float g_proj[4ull * ROWS * HN];

__device__ __forceinline__ float sigmoidf_acc(float v) {
    return 1.f / (1.f + expf(-v));
}

// ---------------------------------------------------------------------------
// tf32 helpers
// ---------------------------------------------------------------------------
__device__ __forceinline__ void split_tf32(float x, unsigned& hi, unsigned& lo) {
    asm("cvt.rna.tf32.f32 %0, %1;" : "=r"(hi) : "f"(x));
    float l = x - __uint_as_float(hi);
    asm("cvt.rna.tf32.f32 %0, %1;" : "=r"(lo) : "f"(l));
}

__device__ __forceinline__ void mma_tf32(float c[4], const unsigned a[4], const unsigned b[2]) {
    asm volatile(
        "mma.sync.aligned.m16n8k8.row.col.f32.tf32.tf32.f32 "
        "{%0,%1,%2,%3},{%4,%5,%6,%7},{%8,%9},{%0,%1,%2,%3};"
        : "+f"(c[0]), "+f"(c[1]), "+f"(c[2]), "+f"(c[3])
        : "r"(a[0]), "r"(a[1]), "r"(a[2]), "r"(a[3]), "r"(b[0]), "r"(b[1]));
}

// ---------------------------------------------------------------------------
// Projection GEMM: C = x @ W^T, tf32 3-way split, pre-split in smem.
// CTA 128x128, BK=8, 256 threads (8 warps: 4m x 2n, warp tile 32x64), occ 2.
// grid = (HN/128, ROWS/128, 4). z==3 applies sigmoid(+b_beta) in epilogue.
// ---------------------------------------------------------------------------
#define GBM 128
#define GBN 128
#define GBK 8
#define SMS 136   // %32 == 8 -> (tig*8 + g) conflict-free fragment reads

__global__ __launch_bounds__(256, 2) void proj_gemm_tc(
    const float* __restrict__ x,
    const float* __restrict__ Wk, const float* __restrict__ Wv,
    const float* __restrict__ Wq, const float* __restrict__ Wb,
    const float* __restrict__ b_beta)
{
    const int z = blockIdx.z;
    const float* __restrict__ W = (z == 0) ? Wk : (z == 1) ? Wv : (z == 2) ? Wq : Wb;
    float* __restrict__ C = g_proj + (size_t)z * ROWS * HN;

    __shared__ unsigned Ah[2][GBK][SMS], Al[2][GBK][SMS];
    __shared__ unsigned Bh[2][GBK][SMS], Bl[2][GBK][SMS];

    const int tid  = threadIdx.x;
    const int lane = tid & 31;
    const int wid  = tid >> 5;
    const int wm   = wid >> 1;        // 0..3 -> 32 rows each
    const int wn   = wid & 1;         // 0..1 -> 64 cols each
    const int g    = lane >> 2;       // 0..7
    const int tig  = lane & 3;        // 0..3

    const int m0 = blockIdx.y * GBM;
    const int n0 = blockIdx.x * GBN;

    // Global load mapping: one float4 of A and one of B per thread per chunk.
    const int lm = tid >> 1;          // 0..127
    const int lk = (tid & 1) * 4;     // 0 or 4
    const float* xA = x + (size_t)(m0 + lm) * DIMK + lk;
    const float* wB = W + (size_t)(n0 + lm) * DIMK + lk;

    float c[2][8][4];
#pragma unroll
    for (int mi = 0; mi < 2; ++mi)
#pragma unroll
        for (int ni = 0; ni < 8; ++ni)
#pragma unroll
            for (int e = 0; e < 4; ++e) c[mi][ni][e] = 0.f;

    float4 ra = *(const float4*)xA;
    float4 rb = *(const float4*)wB;

    // stage: split to tf32 hi/lo once, store both
    {
        const float av[4] = {ra.x, ra.y, ra.z, ra.w};
        const float bv[4] = {rb.x, rb.y, rb.z, rb.w};
#pragma unroll
        for (int jj = 0; jj < 4; ++jj) {
            unsigned hi, lo;
            split_tf32(av[jj], hi, lo);
            Ah[0][lk + jj][lm] = hi;  Al[0][lk + jj][lm] = lo;
            split_tf32(bv[jj], hi, lo);
            Bh[0][lk + jj][lm] = hi;  Bl[0][lk + jj][lm] = lo;
        }
    }
    __syncthreads();

    const int NCH = DIMK / GBK;   // 128
    int buf = 0;
    for (int ch = 0; ch < NCH; ++ch) {
        if (ch + 1 < NCH) {
            const size_t koff = (size_t)(ch + 1) * GBK;
            ra = *(const float4*)(xA + koff);
            rb = *(const float4*)(wB + koff);
        }

        // A fragments for both mi, held across the ni loops
        unsigned ah[2][4], al[2][4];
#pragma unroll
        for (int mi = 0; mi < 2; ++mi) {
            const int mrow = wm * 32 + mi * 16;
            ah[mi][0] = Ah[buf][tig][mrow + g];
            ah[mi][1] = Ah[buf][tig][mrow + g + 8];
            ah[mi][2] = Ah[buf][tig + 4][mrow + g];
            ah[mi][3] = Ah[buf][tig + 4][mrow + g + 8];
            al[mi][0] = Al[buf][tig][mrow + g];
            al[mi][1] = Al[buf][tig][mrow + g + 8];
            al[mi][2] = Al[buf][tig + 4][mrow + g];
            al[mi][3] = Al[buf][tig + 4][mrow + g + 8];
        }

#pragma unroll
        for (int half = 0; half < 2; ++half) {
            unsigned bh[4][2], bl[4][2];
#pragma unroll
            for (int nj = 0; nj < 4; ++nj) {
                const int ncol = wn * 64 + (half * 4 + nj) * 8 + g;
                bh[nj][0] = Bh[buf][tig][ncol];
                bh[nj][1] = Bh[buf][tig + 4][ncol];
                bl[nj][0] = Bl[buf][tig][ncol];
                bl[nj][1] = Bl[buf][tig + 4][ncol];
            }
#pragma unroll
            for (int mi = 0; mi < 2; ++mi)
#pragma unroll
                for (int nj = 0; nj < 4; ++nj) {
                    float* cc = c[mi][half * 4 + nj];
                    mma_tf32(cc, ah[mi], bh[nj]);
                    mma_tf32(cc, ah[mi], bl[nj]);
                    mma_tf32(cc, al[mi], bh[nj]);
                }
        }

        if (ch + 1 < NCH) {
            const float av[4] = {ra.x, ra.y, ra.z, ra.w};
            const float bv[4] = {rb.x, rb.y, rb.z, rb.w};
            const int nb = buf ^ 1;
#pragma unroll
            for (int jj = 0; jj < 4; ++jj) {
                unsigned hi, lo;
                split_tf32(av[jj], hi, lo);
                Ah[nb][lk + jj][lm] = hi;  Al[nb][lk + jj][lm] = lo;
                split_tf32(bv[jj], hi, lo);
                Bh[nb][lk + jj][lm] = hi;  Bl[nb][lk + jj][lm] = lo;
            }
            __syncthreads();
            buf = nb;
        }
    }

    // Epilogue: z==3 applies sigmoid(c + b_beta[col]).
#pragma unroll
    for (int mi = 0; mi < 2; ++mi) {
        const int r0 = m0 + wm * 32 + mi * 16 + g;
#pragma unroll
        for (int ni = 0; ni < 8; ++ni) {
            const int col = n0 + wn * 64 + ni * 8 + 2 * tig;
            float v0 = c[mi][ni][0], v1 = c[mi][ni][1];
            float v2 = c[mi][ni][2], v3 = c[mi][ni][3];
            if (z == 3) {
                const float bb0 = b_beta[col], bb1 = b_beta[col + 1];
                v0 = sigmoidf_acc(v0 + bb0);
                v1 = sigmoidf_acc(v1 + bb1);
                v2 = sigmoidf_acc(v2 + bb0);
                v3 = sigmoidf_acc(v3 + bb1);
            }
            float2* p0 = (float2*)&C[(size_t)r0 * HN + col];
            float2* p1 = (float2*)&C[(size_t)(r0 + 8) * HN + col];
            *p0 = make_float2(v0, v1);
            *p1 = make_float2(v2, v3);
        }
    }
}

// ---------------------------------------------------------------------------
// Fast device math (approx MUFU paths, ~1e-6 abs error)
// ---------------------------------------------------------------------------
__device__ __forceinline__ float fast_ex2(float v) {
    float r;
    asm("ex2.approx.f32 %0, %1;" : "=f"(r) : "f"(v));
    return r;
}
__device__ __forceinline__ float fast_rcp(float v) {
    float r;
    asm("rcp.approx.f32 %0, %1;" : "=f"(r) : "f"(v));
    return r;
}
__device__ __forceinline__ float fast_sqrt(float v) {
    float r;
    asm("sqrt.approx.f32 %0, %1;" : "=f"(r) : "f"(v));
    return r;
}
// tanh(x) = sign(x) * (1-e)/(1+e),  e = 2^(-2*log2(e)*|x|)
__device__ __forceinline__ float fast_tanh(float x) {
    const float ax = fabsf(x);
    const float e  = fast_ex2(ax * -2.885390081777927f);   // e^{-2|x|}
    const float t  = (1.f - e) * fast_rcp(1.f + e);
    return __uint_as_float(__float_as_uint(t) |
                           (__float_as_uint(x) & 0x80000000u));
}
__device__ __forceinline__ float fast_sigmoid(float x) {
    return fast_rcp(1.f + fast_ex2(x * -1.4426950408889634f));
}

// ---------------------------------------------------------------------------
// Sequential scan: one CTA per (b,h). 512 threads; thread owns S row i=tid>>3,
// cols jb..jb+7. Double-buffered staging, 1 barrier/step, merged reductions.
// ---------------------------------------------------------------------------
__global__ __launch_bounds__(512, 1) void scan_kernel(
    const float* __restrict__ S0,
    float* __restrict__ out,
    float* __restrict__ Sfin)
{
    const int bh  = blockIdx.x;
    const int b   = bh >> 3;
    const int h   = bh & 7;
    const int tid = threadIdx.x;
    const int i   = tid >> 3;
    const int jb  = (tid & 7) * 8;

    float S[8];
    const float* S0p = S0 + (size_t)bh * NDIM * NDIM + i * NDIM + jb;
#pragma unroll
    for (int e = 0; e < 8; ++e) S[e] = S0p[e];

    __shared__ float sv[2][4][NDIM];

    const int p = tid >> 6;        // 0..3 selects k/v/q/beta (tid<256)
    const int j = tid & 63;
    const float* myp = g_proj + (size_t)p * ((size_t)ROWS * HN) + b * HN + h * NDIM + j;

    if (tid < 256) sv[0][p][j] = myp[0];
    __syncthreads();

    float* outp = out + (size_t)b * HN + h * NDIM + i;

    for (int t = 0; t < T_STEPS; ++t) {
        float pre = 0.f;
        const bool do_pre = (tid < 256) && (t + 1 < T_STEPS);
        if (do_pre) pre = __ldg(myp + (size_t)(t + 1) * (BATCH * HN));

        const float (*cur)[NDIM] = sv[t & 1];

        float4 k4a = *(const float4*)&cur[0][jb];
        float4 k4b = *(const float4*)&cur[0][jb + 4];
        const float kv[8] = {k4a.x, k4a.y, k4a.z, k4a.w, k4b.x, k4b.y, k4b.z, k4b.w};

        // merged reductions: ss = k.k,  rr = S_i . k  (8-lane row groups)
        float ss = 0.f, rr = 0.f;
#pragma unroll
        for (int e = 0; e < 8; ++e) {
            ss = fmaf(kv[e], kv[e], ss);
            rr = fmaf(S[e], kv[e], rr);
        }
        ss += __shfl_xor_sync(0xffffffffu, ss, 1);
        rr += __shfl_xor_sync(0xffffffffu, rr, 1);
        ss += __shfl_xor_sync(0xffffffffu, ss, 2);
        rr += __shfl_xor_sync(0xffffffffu, rr, 2);
        ss += __shfl_xor_sync(0xffffffffu, ss, 4);
        rr += __shfl_xor_sync(0xffffffffu, rr, 4);

        const float inv   = fast_rcp(fast_sqrt(ss) + 1e-6f);
        const float delta = cur[1][i] - rr * inv;      // v_i - retrieved_i
        const float beta  = cur[3][i];                  // pre-sigmoided
        const float dinv  = delta * inv;

        float4 q4a = *(const float4*)&cur[2][jb];
        float4 q4b = *(const float4*)&cur[2][jb + 4];
        const float qv[8] = {q4a.x, q4a.y, q4a.z, q4a.w, q4b.x, q4b.y, q4b.z, q4b.w};

        float acc = 0.f;
#pragma unroll
        for (int e = 0; e < 8; ++e) {
            float s = fast_tanh(fmaf(dinv, kv[e], beta * S[e]));
            S[e] = s;
            acc = fmaf(s, qv[e], acc);
        }
        acc += __shfl_xor_sync(0xffffffffu, acc, 1);
        acc += __shfl_xor_sync(0xffffffffu, acc, 2);
        acc += __shfl_xor_sync(0xffffffffu, acc, 4);

        if ((tid & 7) == 0) {
            outp[(size_t)t * (BATCH * HN)] = acc * acc * fast_sigmoid(acc);
        }

        if (do_pre) sv[(t + 1) & 1][p][j] = pre;
        __syncthreads();
    }

    if (Sfin != nullptr) {
        float* sp = Sfin + (size_t)bh * NDIM * NDIM + i * NDIM + jb;
#pragma unroll
        for (int e = 0; e < 8; ++e) sp[e] = S[e];
    }
}

// ---------------------------------------------------------------------------
// Inputs: x, S0, W_k, W_v, W_q, W_beta, b_beta
// ---------------------------------------------------------------------------
extern "C" void kernel_launch(void* const* d_in, const int* in_sizes, int n_in,
                              void* d_out, int out_size)
{
    const float* x   = (const float*)d_in[0];
    const float* S0  = (const float*)d_in[1];
    const float* Wk  = (const float*)d_in[2];
    const float* Wv  = (const float*)d_in[3];
    const float* Wq  = (const float*)d_in[4];
    const float* Wb  = (const float*)d_in[5];
    const float* bbt = (const float*)d_in[6];
    float* out = (float*)d_out;

    dim3 gg(HN / GBN, ROWS / GBM, 4);
    proj_gemm_tc<<<gg, 256>>>(x, Wk, Wv, Wq, Wb, bbt);

    float* sfin = nullptr;
    if ((size_t)out_size >= OUT_MAIN + SFIN_ELEMS) sfin = out + OUT_MAIN;

    scan_kernel<<<BATCH * HEADS, 512>>>(S0, out, sfin);
}

// round 5
// speedup vs baseline: 1.5157x; 1.0010x over previous
#include <cuda_runtime.h>
#include <math.h>

// Problem constants
#define T_STEPS 1024
#define BATCH   16
#define DIMK    1024
#define HEADS   8
#define NDIM    64
#define HN      512                 // HEADS*NDIM
#define ROWS    (T_STEPS*BATCH)     // 16384
#define OUT_MAIN ((size_t)T_STEPS*BATCH*HN)        // 8388608
#define SFIN_ELEMS ((size_t)BATCH*HEADS*NDIM*NDIM) // 524288

// Scratch for the 4 projections (k,v,q,beta_sigmoided): 128 MB
__device__ float g_proj[4ull * ROWS * HN];

__device__ __forceinline__ float sigmoidf_acc(float v) {
    return 1.f / (1.f + expf(-v));
}

// ---------------------------------------------------------------------------
// tf32 helpers
// ---------------------------------------------------------------------------
__device__ __forceinline__ void split_tf32(float x, unsigned& hi, unsigned& lo) {
    asm("cvt.rna.tf32.f32 %0, %1;" : "=r"(hi) : "f"(x));
    float l = x - __uint_as_float(hi);
    asm("cvt.rna.tf32.f32 %0, %1;" : "=r"(lo) : "f"(l));
}

__device__ __forceinline__ void mma_tf32(float c[4], const unsigned a[4], const unsigned b[2]) {
    asm volatile(
        "mma.sync.aligned.m16n8k8.row.col.f32.tf32.tf32.f32 "
        "{%0,%1,%2,%3},{%4,%5,%6,%7},{%8,%9},{%0,%1,%2,%3};"
        : "+f"(c[0]), "+f"(c[1]), "+f"(c[2]), "+f"(c[3])
        : "r"(a[0]), "r"(a[1]), "r"(a[2]), "r"(a[3]), "r"(b[0]), "r"(b[1]));
}

// ---------------------------------------------------------------------------
// Projection GEMM: C = x @ W^T, tf32 3-way split, pre-split in smem.
// CTA 128x128, BK=8, 256 threads (8 warps: 4m x 2n, warp tile 32x64), occ 2.
// grid = (HN/128, ROWS/128, 4). z==3 applies sigmoid(+b_beta) in epilogue.
// ---------------------------------------------------------------------------
#define GBM 128
#define GBN 128
#define GBK 8
#define SMS 136   // %32 == 8 -> (tig*8 + g) conflict-free fragment reads

__global__ __launch_bounds__(256, 2) void proj_gemm_tc(
    const float* __restrict__ x,
    const float* __restrict__ Wk, const float* __restrict__ Wv,
    const float* __restrict__ Wq, const float* __restrict__ Wb,
    const float* __restrict__ b_beta)
{
    const int z = blockIdx.z;
    const float* __restrict__ W = (z == 0) ? Wk : (z == 1) ? Wv : (z == 2) ? Wq : Wb;
    float* __restrict__ C = g_proj + (size_t)z * ROWS * HN;

    __shared__ unsigned Ah[2][GBK][SMS], Al[2][GBK][SMS];
    __shared__ unsigned Bh[2][GBK][SMS], Bl[2][GBK][SMS];

    const int tid  = threadIdx.x;
    const int lane = tid & 31;
    const int wid  = tid >> 5;
    const int wm   = wid >> 1;        // 0..3 -> 32 rows each
    const int wn   = wid & 1;         // 0..1 -> 64 cols each
    const int g    = lane >> 2;       // 0..7
    const int tig  = lane & 3;        // 0..3

    const int m0 = blockIdx.y * GBM;
    const int n0 = blockIdx.x * GBN;

    // Global load mapping: one float4 of A and one of B per thread per chunk.
    const int lm = tid >> 1;          // 0..127
    const int lk = (tid & 1) * 4;     // 0 or 4
    const float* xA = x + (size_t)(m0 + lm) * DIMK + lk;
    const float* wB = W + (size_t)(n0 + lm) * DIMK + lk;

    float c[2][8][4];
#pragma unroll
    for (int mi = 0; mi < 2; ++mi)
#pragma unroll
        for (int ni = 0; ni < 8; ++ni)
#pragma unroll
            for (int e = 0; e < 4; ++e) c[mi][ni][e] = 0.f;

    float4 ra = *(const float4*)xA;
    float4 rb = *(const float4*)wB;

    // stage: split to tf32 hi/lo once, store both
    {
        const float av[4] = {ra.x, ra.y, ra.z, ra.w};
        const float bv[4] = {rb.x, rb.y, rb.z, rb.w};
#pragma unroll
        for (int jj = 0; jj < 4; ++jj) {
            unsigned hi, lo;
            split_tf32(av[jj], hi, lo);
            Ah[0][lk + jj][lm] = hi;  Al[0][lk + jj][lm] = lo;
            split_tf32(bv[jj], hi, lo);
            Bh[0][lk + jj][lm] = hi;  Bl[0][lk + jj][lm] = lo;
        }
    }
    __syncthreads();

    const int NCH = DIMK / GBK;   // 128
    int buf = 0;
    for (int ch = 0; ch < NCH; ++ch) {
        if (ch + 1 < NCH) {
            const size_t koff = (size_t)(ch + 1) * GBK;
            ra = *(const float4*)(xA + koff);
            rb = *(const float4*)(wB + koff);
        }

        // A fragments for both mi, held across the ni loops
        unsigned ah[2][4], al[2][4];
#pragma unroll
        for (int mi = 0; mi < 2; ++mi) {
            const int mrow = wm * 32 + mi * 16;
            ah[mi][0] = Ah[buf][tig][mrow + g];
            ah[mi][1] = Ah[buf][tig][mrow + g + 8];
            ah[mi][2] = Ah[buf][tig + 4][mrow + g];
            ah[mi][3] = Ah[buf][tig + 4][mrow + g + 8];
            al[mi][0] = Al[buf][tig][mrow + g];
            al[mi][1] = Al[buf][tig][mrow + g + 8];
            al[mi][2] = Al[buf][tig + 4][mrow + g];
            al[mi][3] = Al[buf][tig + 4][mrow + g + 8];
        }

#pragma unroll
        for (int half = 0; half < 2; ++half) {
            unsigned bh[4][2], bl[4][2];
#pragma unroll
            for (int nj = 0; nj < 4; ++nj) {
                const int ncol = wn * 64 + (half * 4 + nj) * 8 + g;
                bh[nj][0] = Bh[buf][tig][ncol];
                bh[nj][1] = Bh[buf][tig + 4][ncol];
                bl[nj][0] = Bl[buf][tig][ncol];
                bl[nj][1] = Bl[buf][tig + 4][ncol];
            }
#pragma unroll
            for (int mi = 0; mi < 2; ++mi)
#pragma unroll
                for (int nj = 0; nj < 4; ++nj) {
                    float* cc = c[mi][half * 4 + nj];
                    mma_tf32(cc, ah[mi], bh[nj]);
                    mma_tf32(cc, ah[mi], bl[nj]);
                    mma_tf32(cc, al[mi], bh[nj]);
                }
        }

        if (ch + 1 < NCH) {
            const float av[4] = {ra.x, ra.y, ra.z, ra.w};
            const float bv[4] = {rb.x, rb.y, rb.z, rb.w};
            const int nb = buf ^ 1;
#pragma unroll
            for (int jj = 0; jj < 4; ++jj) {
                unsigned hi, lo;
                split_tf32(av[jj], hi, lo);
                Ah[nb][lk + jj][lm] = hi;  Al[nb][lk + jj][lm] = lo;
                split_tf32(bv[jj], hi, lo);
                Bh[nb][lk + jj][lm] = hi;  Bl[nb][lk + jj][lm] = lo;
            }
            __syncthreads();
            buf = nb;
        }
    }

    // Epilogue: z==3 applies sigmoid(c + b_beta[col]).
#pragma unroll
    for (int mi = 0; mi < 2; ++mi) {
        const int r0 = m0 + wm * 32 + mi * 16 + g;
#pragma unroll
        for (int ni = 0; ni < 8; ++ni) {
            const int col = n0 + wn * 64 + ni * 8 + 2 * tig;
            float v0 = c[mi][ni][0], v1 = c[mi][ni][1];
            float v2 = c[mi][ni][2], v3 = c[mi][ni][3];
            if (z == 3) {
                const float bb0 = b_beta[col], bb1 = b_beta[col + 1];
                v0 = sigmoidf_acc(v0 + bb0);
                v1 = sigmoidf_acc(v1 + bb1);
                v2 = sigmoidf_acc(v2 + bb0);
                v3 = sigmoidf_acc(v3 + bb1);
            }
            float2* p0 = (float2*)&C[(size_t)r0 * HN + col];
            float2* p1 = (float2*)&C[(size_t)(r0 + 8) * HN + col];
            *p0 = make_float2(v0, v1);
            *p1 = make_float2(v2, v3);
        }
    }
}

// ---------------------------------------------------------------------------
// Fast device math (approx MUFU paths, ~1e-6 abs error)
// ---------------------------------------------------------------------------
__device__ __forceinline__ float fast_ex2(float v) {
    float r;
    asm("ex2.approx.f32 %0, %1;" : "=f"(r) : "f"(v));
    return r;
}
__device__ __forceinline__ float fast_rcp(float v) {
    float r;
    asm("rcp.approx.f32 %0, %1;" : "=f"(r) : "f"(v));
    return r;
}
__device__ __forceinline__ float fast_sqrt(float v) {
    float r;
    asm("sqrt.approx.f32 %0, %1;" : "=f"(r) : "f"(v));
    return r;
}
// tanh(x) = sign(x) * (1-e)/(1+e),  e = 2^(-2*log2(e)*|x|)
__device__ __forceinline__ float fast_tanh(float x) {
    const float ax = fabsf(x);
    const float e  = fast_ex2(ax * -2.885390081777927f);   // e^{-2|x|}
    const float t  = (1.f - e) * fast_rcp(1.f + e);
    return __uint_as_float(__float_as_uint(t) |
                           (__float_as_uint(x) & 0x80000000u));
}
__device__ __forceinline__ float fast_sigmoid(float x) {
    return fast_rcp(1.f + fast_ex2(x * -1.4426950408889634f));
}

// ---------------------------------------------------------------------------
// Sequential scan: one CTA per (b,h). 512 threads; thread owns S row i=tid>>3,
// cols jb..jb+7. Double-buffered staging, 1 barrier/step, merged reductions.
// ---------------------------------------------------------------------------
__global__ __launch_bounds__(512, 1) void scan_kernel(
    const float* __restrict__ S0,
    float* __restrict__ out,
    float* __restrict__ Sfin)
{
    const int bh  = blockIdx.x;
    const int b   = bh >> 3;
    const int h   = bh & 7;
    const int tid = threadIdx.x;
    const int i   = tid >> 3;
    const int jb  = (tid & 7) * 8;

    float S[8];
    const float* S0p = S0 + (size_t)bh * NDIM * NDIM + i * NDIM + jb;
#pragma unroll
    for (int e = 0; e < 8; ++e) S[e] = S0p[e];

    __shared__ float sv[2][4][NDIM];

    const int p = tid >> 6;        // 0..3 selects k/v/q/beta (tid<256)
    const int j = tid & 63;
    const float* myp = g_proj + (size_t)p * ((size_t)ROWS * HN) + b * HN + h * NDIM + j;

    if (tid < 256) sv[0][p][j] = myp[0];
    __syncthreads();

    float* outp = out + (size_t)b * HN + h * NDIM + i;

    for (int t = 0; t < T_STEPS; ++t) {
        float pre = 0.f;
        const bool do_pre = (tid < 256) && (t + 1 < T_STEPS);
        if (do_pre) pre = __ldg(myp + (size_t)(t + 1) * (BATCH * HN));

        const float (*cur)[NDIM] = sv[t & 1];

        float4 k4a = *(const float4*)&cur[0][jb];
        float4 k4b = *(const float4*)&cur[0][jb + 4];
        const float kv[8] = {k4a.x, k4a.y, k4a.z, k4a.w, k4b.x, k4b.y, k4b.z, k4b.w};

        // merged reductions: ss = k.k,  rr = S_i . k  (8-lane row groups)
        float ss = 0.f, rr = 0.f;
#pragma unroll
        for (int e = 0; e < 8; ++e) {
            ss = fmaf(kv[e], kv[e], ss);
            rr = fmaf(S[e], kv[e], rr);
        }
        ss += __shfl_xor_sync(0xffffffffu, ss, 1);
        rr += __shfl_xor_sync(0xffffffffu, rr, 1);
        ss += __shfl_xor_sync(0xffffffffu, ss, 2);
        rr += __shfl_xor_sync(0xffffffffu, rr, 2);
        ss += __shfl_xor_sync(0xffffffffu, ss, 4);
        rr += __shfl_xor_sync(0xffffffffu, rr, 4);

        const float inv   = fast_rcp(fast_sqrt(ss) + 1e-6f);
        const float delta = cur[1][i] - rr * inv;      // v_i - retrieved_i
        const float beta  = cur[3][i];                  // pre-sigmoided
        const float dinv  = delta * inv;

        float4 q4a = *(const float4*)&cur[2][jb];
        float4 q4b = *(const float4*)&cur[2][jb + 4];
        const float qv[8] = {q4a.x, q4a.y, q4a.z, q4a.w, q4b.x, q4b.y, q4b.z, q4b.w};

        float acc = 0.f;
#pragma unroll
        for (int e = 0; e < 8; ++e) {
            float s = fast_tanh(fmaf(dinv, kv[e], beta * S[e]));
            S[e] = s;
            acc = fmaf(s, qv[e], acc);
        }
        acc += __shfl_xor_sync(0xffffffffu, acc, 1);
        acc += __shfl_xor_sync(0xffffffffu, acc, 2);
        acc += __shfl_xor_sync(0xffffffffu, acc, 4);

        if ((tid & 7) == 0) {
            outp[(size_t)t * (BATCH * HN)] = acc * acc * fast_sigmoid(acc);
        }

        if (do_pre) sv[(t + 1) & 1][p][j] = pre;
        __syncthreads();
    }

    if (Sfin != nullptr) {
        float* sp = Sfin + (size_t)bh * NDIM * NDIM + i * NDIM + jb;
#pragma unroll
        for (int e = 0; e < 8; ++e) sp[e] = S[e];
    }
}

// ---------------------------------------------------------------------------
// Inputs: x, S0, W_k, W_v, W_q, W_beta, b_beta
// ---------------------------------------------------------------------------
extern "C" void kernel_launch(void* const* d_in, const int* in_sizes, int n_in,
                              void* d_out, int out_size)
{
    const float* x   = (const float*)d_in[0];
    const float* S0  = (const float*)d_in[1];
    const float* Wk  = (const float*)d_in[2];
    const float* Wv  = (const float*)d_in[3];
    const float* Wq  = (const float*)d_in[4];
    const float* Wb  = (const float*)d_in[5];
    const float* bbt = (const float*)d_in[6];
    float* out = (float*)d_out;

    dim3 gg(HN / GBN, ROWS / GBM, 4);
    proj_gemm_tc<<<gg, 256>>>(x, Wk, Wv, Wq, Wb, bbt);

    float* sfin = nullptr;
    if ((size_t)out_size >= OUT_MAIN + SFIN_ELEMS) sfin = out + OUT_MAIN;

    scan_kernel<<<BATCH * HEADS, 512>>>(S0, out, sfin);
}

// round 6
// speedup vs baseline: 1.6477x; 1.0870x over previous
#include <cuda_runtime.h>
#include <math.h>

// Problem constants
#define T_STEPS 1024
#define BATCH   16
#define DIMK    1024
#define HEADS   8
#define NDIM    64
#define HN      512                 // HEADS*NDIM
#define ROWS    (T_STEPS*BATCH)     // 16384
#define OUT_MAIN ((size_t)T_STEPS*BATCH*HN)        // 8388608
#define SFIN_ELEMS ((size_t)BATCH*HEADS*NDIM*NDIM) // 524288

// Scratch for the 4 projections (k,v,q,beta_sigmoided): 128 MB
__device__ float g_proj[4ull * ROWS * HN];

__device__ __forceinline__ float sigmoidf_acc(float v) {
    return 1.f / (1.f + expf(-v));
}

// ---------------------------------------------------------------------------
// tf32 helpers
// ---------------------------------------------------------------------------
__device__ __forceinline__ void split_tf32(float x, unsigned& hi, unsigned& lo) {
    asm("cvt.rna.tf32.f32 %0, %1;" : "=r"(hi) : "f"(x));
    float l = x - __uint_as_float(hi);
    asm("cvt.rna.tf32.f32 %0, %1;" : "=r"(lo) : "f"(l));
}

__device__ __forceinline__ void mma_tf32(float c[4], const unsigned a[4], const unsigned b[2]) {
    asm volatile(
        "mma.sync.aligned.m16n8k8.row.col.f32.tf32.tf32.f32 "
        "{%0,%1,%2,%3},{%4,%5,%6,%7},{%8,%9},{%0,%1,%2,%3};"
        : "+f"(c[0]), "+f"(c[1]), "+f"(c[2]), "+f"(c[3])
        : "r"(a[0]), "r"(a[1]), "r"(a[2]), "r"(a[3]), "r"(b[0]), "r"(b[1]));
}

// ---------------------------------------------------------------------------
// Projection GEMM (unchanged from R5 — passing; tcgen05 is next round's lever)
// ---------------------------------------------------------------------------
#define GBM 128
#define GBN 128
#define GBK 8
#define SMS 136

__global__ __launch_bounds__(256, 2) void proj_gemm_tc(
    const float* __restrict__ x,
    const float* __restrict__ Wk, const float* __restrict__ Wv,
    const float* __restrict__ Wq, const float* __restrict__ Wb,
    const float* __restrict__ b_beta)
{
    const int z = blockIdx.z;
    const float* __restrict__ W = (z == 0) ? Wk : (z == 1) ? Wv : (z == 2) ? Wq : Wb;
    float* __restrict__ C = g_proj + (size_t)z * ROWS * HN;

    __shared__ unsigned Ah[2][GBK][SMS], Al[2][GBK][SMS];
    __shared__ unsigned Bh[2][GBK][SMS], Bl[2][GBK][SMS];

    const int tid  = threadIdx.x;
    const int lane = tid & 31;
    const int wid  = tid >> 5;
    const int wm   = wid >> 1;
    const int wn   = wid & 1;
    const int g    = lane >> 2;
    const int tig  = lane & 3;

    const int m0 = blockIdx.y * GBM;
    const int n0 = blockIdx.x * GBN;

    const int lm = tid >> 1;
    const int lk = (tid & 1) * 4;
    const float* xA = x + (size_t)(m0 + lm) * DIMK + lk;
    const float* wB = W + (size_t)(n0 + lm) * DIMK + lk;

    float c[2][8][4];
#pragma unroll
    for (int mi = 0; mi < 2; ++mi)
#pragma unroll
        for (int ni = 0; ni < 8; ++ni)
#pragma unroll
            for (int e = 0; e < 4; ++e) c[mi][ni][e] = 0.f;

    float4 ra = *(const float4*)xA;
    float4 rb = *(const float4*)wB;

    {
        const float av[4] = {ra.x, ra.y, ra.z, ra.w};
        const float bv[4] = {rb.x, rb.y, rb.z, rb.w};
#pragma unroll
        for (int jj = 0; jj < 4; ++jj) {
            unsigned hi, lo;
            split_tf32(av[jj], hi, lo);
            Ah[0][lk + jj][lm] = hi;  Al[0][lk + jj][lm] = lo;
            split_tf32(bv[jj], hi, lo);
            Bh[0][lk + jj][lm] = hi;  Bl[0][lk + jj][lm] = lo;
        }
    }
    __syncthreads();

    const int NCH = DIMK / GBK;
    int buf = 0;
    for (int ch = 0; ch < NCH; ++ch) {
        if (ch + 1 < NCH) {
            const size_t koff = (size_t)(ch + 1) * GBK;
            ra = *(const float4*)(xA + koff);
            rb = *(const float4*)(wB + koff);
        }

        unsigned ah[2][4], al[2][4];
#pragma unroll
        for (int mi = 0; mi < 2; ++mi) {
            const int mrow = wm * 32 + mi * 16;
            ah[mi][0] = Ah[buf][tig][mrow + g];
            ah[mi][1] = Ah[buf][tig][mrow + g + 8];
            ah[mi][2] = Ah[buf][tig + 4][mrow + g];
            ah[mi][3] = Ah[buf][tig + 4][mrow + g + 8];
            al[mi][0] = Al[buf][tig][mrow + g];
            al[mi][1] = Al[buf][tig][mrow + g + 8];
            al[mi][2] = Al[buf][tig + 4][mrow + g];
            al[mi][3] = Al[buf][tig + 4][mrow + g + 8];
        }

#pragma unroll
        for (int half = 0; half < 2; ++half) {
            unsigned bh[4][2], bl[4][2];
#pragma unroll
            for (int nj = 0; nj < 4; ++nj) {
                const int ncol = wn * 64 + (half * 4 + nj) * 8 + g;
                bh[nj][0] = Bh[buf][tig][ncol];
                bh[nj][1] = Bh[buf][tig + 4][ncol];
                bl[nj][0] = Bl[buf][tig][ncol];
                bl[nj][1] = Bl[buf][tig + 4][ncol];
            }
#pragma unroll
            for (int mi = 0; mi < 2; ++mi)
#pragma unroll
                for (int nj = 0; nj < 4; ++nj) {
                    float* cc = c[mi][half * 4 + nj];
                    mma_tf32(cc, ah[mi], bh[nj]);
                    mma_tf32(cc, ah[mi], bl[nj]);
                    mma_tf32(cc, al[mi], bh[nj]);
                }
        }

        if (ch + 1 < NCH) {
            const float av[4] = {ra.x, ra.y, ra.z, ra.w};
            const float bv[4] = {rb.x, rb.y, rb.z, rb.w};
            const int nb = buf ^ 1;
#pragma unroll
            for (int jj = 0; jj < 4; ++jj) {
                unsigned hi, lo;
                split_tf32(av[jj], hi, lo);
                Ah[nb][lk + jj][lm] = hi;  Al[nb][lk + jj][lm] = lo;
                split_tf32(bv[jj], hi, lo);
                Bh[nb][lk + jj][lm] = hi;  Bl[nb][lk + jj][lm] = lo;
            }
            __syncthreads();
            buf = nb;
        }
    }

#pragma unroll
    for (int mi = 0; mi < 2; ++mi) {
        const int r0 = m0 + wm * 32 + mi * 16 + g;
#pragma unroll
        for (int ni = 0; ni < 8; ++ni) {
            const int col = n0 + wn * 64 + ni * 8 + 2 * tig;
            float v0 = c[mi][ni][0], v1 = c[mi][ni][1];
            float v2 = c[mi][ni][2], v3 = c[mi][ni][3];
            if (z == 3) {
                const float bb0 = b_beta[col], bb1 = b_beta[col + 1];
                v0 = sigmoidf_acc(v0 + bb0);
                v1 = sigmoidf_acc(v1 + bb1);
                v2 = sigmoidf_acc(v2 + bb0);
                v3 = sigmoidf_acc(v3 + bb1);
            }
            float2* p0 = (float2*)&C[(size_t)r0 * HN + col];
            float2* p1 = (float2*)&C[(size_t)(r0 + 8) * HN + col];
            *p0 = make_float2(v0, v1);
            *p1 = make_float2(v2, v3);
        }
    }
}

// ---------------------------------------------------------------------------
// Fast device math (approx MUFU paths)
// ---------------------------------------------------------------------------
__device__ __forceinline__ float fast_ex2(float v) {
    float r;  asm("ex2.approx.f32 %0, %1;" : "=f"(r) : "f"(v));  return r;
}
__device__ __forceinline__ float fast_rcp(float v) {
    float r;  asm("rcp.approx.f32 %0, %1;" : "=f"(r) : "f"(v));  return r;
}
__device__ __forceinline__ float fast_sqrt(float v) {
    float r;  asm("sqrt.approx.f32 %0, %1;" : "=f"(r) : "f"(v));  return r;
}
__device__ __forceinline__ float fast_tanh(float x) {
    const float ax = fabsf(x);
    const float e  = fast_ex2(ax * -2.885390081777927f);   // e^{-2|x|}
    const float t  = (1.f - e) * fast_rcp(1.f + e);
    return __uint_as_float(__float_as_uint(t) |
                           (__float_as_uint(x) & 0x80000000u));
}
__device__ __forceinline__ float fast_sigmoid(float x) {
    return fast_rcp(1.f + fast_ex2(x * -1.4426950408889634f));
}

// ---------------------------------------------------------------------------
// Barrier-free scan. One CTA per (b,h); 16 warps; warp w owns rows 4w..4w+3.
// Lane l: row = 4w + (l>>3), col group jb = (l&7)*8.  Rows are fully
// independent given the per-step k/v/q/beta streams, which every warp reads
// itself from gmem (same addresses -> L1 broadcast). No smem, no barriers;
// warps free-run and drift fills issue/MUFU bubbles. t+1 inputs prefetched
// into registers so gmem latency hides under the tanh chain.
// ---------------------------------------------------------------------------
__global__ __launch_bounds__(512, 1) void scan_kernel(
    const float* __restrict__ S0,
    float* __restrict__ out,
    float* __restrict__ Sfin)
{
    const int bh   = blockIdx.x;
    const int b    = bh >> 3;
    const int h    = bh & 7;
    const int tid  = threadIdx.x;
    const int w    = tid >> 5;
    const int lane = tid & 31;
    const int row  = w * 4 + (lane >> 3);   // 0..63
    const int jb   = (lane & 7) * 8;        // col base

    float S[8];
    const float* S0p = S0 + (size_t)bh * NDIM * NDIM + row * NDIM + jb;
#pragma unroll
    for (int e = 0; e < 8; ++e) S[e] = S0p[e];

    const size_t slab = (size_t)ROWS * HN;
    const size_t step = (size_t)BATCH * HN;        // 8192 floats per t
    const float* pk = g_proj + 0 * slab + (size_t)b * HN + h * NDIM;
    const float* pv = g_proj + 1 * slab + (size_t)b * HN + h * NDIM;
    const float* pq = g_proj + 2 * slab + (size_t)b * HN + h * NDIM;
    const float* pb = g_proj + 3 * slab + (size_t)b * HN + h * NDIM;

    // current-step inputs in registers
    float4 kc0 = *(const float4*)(pk + jb);
    float4 kc1 = *(const float4*)(pk + jb + 4);
    float4 qc0 = *(const float4*)(pq + jb);
    float4 qc1 = *(const float4*)(pq + jb + 4);
    float  vc  = pv[row];
    float  bc  = pb[row];

    float* outp = out + (size_t)b * HN + h * NDIM + row;

    for (int t = 0; t < T_STEPS; ++t) {
        // prefetch t+1 (independent of this step's compute)
        float4 kp0, kp1, qp0, qp1;
        float  vp = 0.f, bp = 0.f;
        if (t + 1 < T_STEPS) {
            const size_t o = (size_t)(t + 1) * step;
            kp0 = *(const float4*)(pk + o + jb);
            kp1 = *(const float4*)(pk + o + jb + 4);
            qp0 = *(const float4*)(pq + o + jb);
            qp1 = *(const float4*)(pq + o + jb + 4);
            vp  = __ldg(pv + o + row);
            bp  = __ldg(pb + o + row);
        } else {
            kp0 = kc0; kp1 = kc1; qp0 = qc0; qp1 = qc1;
        }

        const float kv[8] = {kc0.x, kc0.y, kc0.z, kc0.w, kc1.x, kc1.y, kc1.z, kc1.w};

        // merged 8-lane reductions: ss = k.k (same in all row groups), rr = S_row . k
        float ss = 0.f, rr = 0.f;
#pragma unroll
        for (int e = 0; e < 8; ++e) {
            ss = fmaf(kv[e], kv[e], ss);
            rr = fmaf(S[e], kv[e], rr);
        }
        ss += __shfl_xor_sync(0xffffffffu, ss, 1);
        rr += __shfl_xor_sync(0xffffffffu, rr, 1);
        ss += __shfl_xor_sync(0xffffffffu, ss, 2);
        rr += __shfl_xor_sync(0xffffffffu, rr, 2);
        ss += __shfl_xor_sync(0xffffffffu, ss, 4);
        rr += __shfl_xor_sync(0xffffffffu, rr, 4);

        const float inv   = fast_rcp(fast_sqrt(ss) + 1e-6f);
        const float delta = vc - rr * inv;
        const float dinv  = delta * inv;
        const float beta  = bc;          // pre-sigmoided in GEMM epilogue

        const float qv[8] = {qc0.x, qc0.y, qc0.z, qc0.w, qc1.x, qc1.y, qc1.z, qc1.w};

        float acc = 0.f;
#pragma unroll
        for (int e = 0; e < 8; ++e) {
            float s = fast_tanh(fmaf(dinv, kv[e], beta * S[e]));
            S[e] = s;
            acc = fmaf(s, qv[e], acc);
        }
        acc += __shfl_xor_sync(0xffffffffu, acc, 1);
        acc += __shfl_xor_sync(0xffffffffu, acc, 2);
        acc += __shfl_xor_sync(0xffffffffu, acc, 4);

        if ((lane & 7) == 0) {
            outp[(size_t)t * step] = acc * acc * fast_sigmoid(acc);
        }

        kc0 = kp0; kc1 = kp1; qc0 = qp0; qc1 = qp1; vc = vp; bc = bp;
    }

    if (Sfin != nullptr) {
        float* sp = Sfin + (size_t)bh * NDIM * NDIM + row * NDIM + jb;
#pragma unroll
        for (int e = 0; e < 8; ++e) sp[e] = S[e];
    }
}

// ---------------------------------------------------------------------------
// Inputs: x, S0, W_k, W_v, W_q, W_beta, b_beta
// ---------------------------------------------------------------------------
extern "C" void kernel_launch(void* const* d_in, const int* in_sizes, int n_in,
                              void* d_out, int out_size)
{
    const float* x   = (const float*)d_in[0];
    const float* S0  = (const float*)d_in[1];
    const float* Wk  = (const float*)d_in[2];
    const float* Wv  = (const float*)d_in[3];
    const float* Wq  = (const float*)d_in[4];
    const float* Wb  = (const float*)d_in[5];
    const float* bbt = (const float*)d_in[6];
    float* out = (float*)d_out;

    dim3 gg(HN / GBN, ROWS / GBM, 4);
    proj_gemm_tc<<<gg, 256>>>(x, Wk, Wv, Wq, Wb, bbt);

    float* sfin = nullptr;
    if ((size_t)out_size >= OUT_MAIN + SFIN_ELEMS) sfin = out + OUT_MAIN;

    scan_kernel<<<BATCH * HEADS, 512>>>(S0, out, sfin);
}

// round 9
// speedup vs baseline: 2.0737x; 1.2586x over previous
#include <cuda_runtime.h>
#include <cuda_bf16.h>
#include <math.h>
#include <stdint.h>

// Problem constants
#define T_STEPS 1024
#define BATCH   16
#define DIMK    1024
#define HEADS   8
#define NDIM    64
#define HN      512                 // HEADS*NDIM
#define ROWS    (T_STEPS*BATCH)     // 16384
#define OUT_MAIN ((size_t)T_STEPS*BATCH*HN)        // 8388608
#define SFIN_ELEMS ((size_t)BATCH*HEADS*NDIM*NDIM) // 524288

// Scratch for the 4 projections (k,v,q,beta_sigmoided): 128 MB
__device__ float g_proj[4ull * ROWS * HN];

__device__ __forceinline__ float sigmoidf_acc(float v) {
    return 1.f / (1.f + expf(-v));
}

// ---------------------------------------------------------------------------
// bf16 split helpers: x = hi + lo (each bf16); 3-term mma recovers ~2^-18.
// Pairs are packed along K: low 16 bits = even k, high 16 bits = odd k.
// ---------------------------------------------------------------------------
__device__ __forceinline__ void split_bf16_pair(float f0, float f1,
                                                uint32_t& hi, uint32_t& lo) {
    __nv_bfloat162 hp = __floats2bfloat162_rn(f0, f1);
    hi = *reinterpret_cast<uint32_t*>(&hp);
    float l0 = f0 - __low2float(hp);
    float l1 = f1 - __high2float(hp);
    __nv_bfloat162 lp = __floats2bfloat162_rn(l0, l1);
    lo = *reinterpret_cast<uint32_t*>(&lp);
}

__device__ __forceinline__ void mma_bf16(float c[4], const uint32_t a[4],
                                         const uint32_t b[2]) {
    asm volatile(
        "mma.sync.aligned.m16n8k16.row.col.f32.bf16.bf16.f32 "
        "{%0,%1,%2,%3},{%4,%5,%6,%7},{%8,%9},{%0,%1,%2,%3};"
        : "+f"(c[0]), "+f"(c[1]), "+f"(c[2]), "+f"(c[3])
        : "r"(a[0]), "r"(a[1]), "r"(a[2]), "r"(a[3]), "r"(b[0]), "r"(b[1]));
}

// ---------------------------------------------------------------------------
// Projection GEMM: C[m,n] = sum_k x[m,k] * W[n,k], 3x bf16 split.
// CTA tile 128x128, K-chunk = 16 floats (8 packed u32 rows), 256 threads
// (8 warps: 4m x 2n, warp tile 32x64), double-buffered smem, occ 2.
// grid = (HN/128, ROWS/128, 4). z==3 applies sigmoid(+b_beta) in epilogue.
// ---------------------------------------------------------------------------
#define GBM 128
#define GBN 128
#define KF  16            // floats of K per chunk
#define KU  8             // packed u32 rows per chunk
#define SMS 136           // row stride (u32): (tig*136+g) % 32 all distinct

__global__ __launch_bounds__(256, 2) void proj_gemm_bf16(
    const float* __restrict__ x,
    const float* __restrict__ Wk, const float* __restrict__ Wv,
    const float* __restrict__ Wq, const float* __restrict__ Wb,
    const float* __restrict__ b_beta)
{
    const int z = blockIdx.z;
    const float* __restrict__ W = (z == 0) ? Wk : (z == 1) ? Wv : (z == 2) ? Wq : Wb;
    float* __restrict__ C = g_proj + (size_t)z * ROWS * HN;

    __shared__ uint32_t Ah[2][KU][SMS], Al[2][KU][SMS];
    __shared__ uint32_t Bh[2][KU][SMS], Bl[2][KU][SMS];

    const int tid  = threadIdx.x;
    const int lane = tid & 31;
    const int wid  = tid >> 5;
    const int wm   = wid >> 1;        // 0..3 -> 32 rows each
    const int wn   = wid & 1;         // 0..1 -> 64 cols each
    const int g    = lane >> 2;       // 0..7
    const int tig  = lane & 3;        // 0..3

    const int m0 = blockIdx.y * GBM;
    const int n0 = blockIdx.x * GBN;

    // Loads: thread -> row lm (0..127), float offset lkf (0 or 8): 8 floats each
    const int lm  = tid >> 1;
    const int lkf = (tid & 1) * 8;
    const int k2b = lkf >> 1;         // packed row base: 0 or 4
    const float* xA = x + (size_t)(m0 + lm) * DIMK + lkf;
    const float* wB = W + (size_t)(n0 + lm) * DIMK + lkf;

    float c[2][8][4];
#pragma unroll
    for (int mi = 0; mi < 2; ++mi)
#pragma unroll
        for (int ni = 0; ni < 8; ++ni)
#pragma unroll
            for (int e = 0; e < 4; ++e) c[mi][ni][e] = 0.f;

    float4 ra0 = *(const float4*)(xA);
    float4 ra1 = *(const float4*)(xA + 4);
    float4 rb0 = *(const float4*)(wB);
    float4 rb1 = *(const float4*)(wB + 4);

    // split + pack one chunk into stage s
    auto store_stage = [&](int s, float4 a0, float4 a1, float4 b0, float4 b1) {
        const float fa[8] = {a0.x, a0.y, a0.z, a0.w, a1.x, a1.y, a1.z, a1.w};
        const float fb[8] = {b0.x, b0.y, b0.z, b0.w, b1.x, b1.y, b1.z, b1.w};
#pragma unroll
        for (int j = 0; j < 4; ++j) {
            uint32_t hi, lo;
            split_bf16_pair(fa[2 * j], fa[2 * j + 1], hi, lo);
            Ah[s][k2b + j][lm] = hi;  Al[s][k2b + j][lm] = lo;
            split_bf16_pair(fb[2 * j], fb[2 * j + 1], hi, lo);
            Bh[s][k2b + j][lm] = hi;  Bl[s][k2b + j][lm] = lo;
        }
    };

    store_stage(0, ra0, ra1, rb0, rb1);
    __syncthreads();

    const int NCH = DIMK / KF;   // 64
    int buf = 0;
    for (int ch = 0; ch < NCH; ++ch) {
        if (ch + 1 < NCH) {
            const size_t koff = (size_t)(ch + 1) * KF;
            ra0 = *(const float4*)(xA + koff);
            ra1 = *(const float4*)(xA + koff + 4);
            rb0 = *(const float4*)(wB + koff);
            rb1 = *(const float4*)(wB + koff + 4);
        }

        // A fragments (m16n8k16): a0=(g,tig) a1=(g+8,tig) a2=(g,tig+4) a3=(g+8,tig+4)
        uint32_t ah[2][4], al[2][4];
#pragma unroll
        for (int mi = 0; mi < 2; ++mi) {
            const int mrow = wm * 32 + mi * 16;
            ah[mi][0] = Ah[buf][tig][mrow + g];
            ah[mi][1] = Ah[buf][tig][mrow + g + 8];
            ah[mi][2] = Ah[buf][tig + 4][mrow + g];
            ah[mi][3] = Ah[buf][tig + 4][mrow + g + 8];
            al[mi][0] = Al[buf][tig][mrow + g];
            al[mi][1] = Al[buf][tig][mrow + g + 8];
            al[mi][2] = Al[buf][tig + 4][mrow + g];
            al[mi][3] = Al[buf][tig + 4][mrow + g + 8];
        }

#pragma unroll
        for (int half = 0; half < 2; ++half) {
            uint32_t bh[4][2], bl[4][2];
#pragma unroll
            for (int nj = 0; nj < 4; ++nj) {
                const int ncol = wn * 64 + (half * 4 + nj) * 8 + g;
                bh[nj][0] = Bh[buf][tig][ncol];
                bh[nj][1] = Bh[buf][tig + 4][ncol];
                bl[nj][0] = Bl[buf][tig][ncol];
                bl[nj][1] = Bl[buf][tig + 4][ncol];
            }
#pragma unroll
            for (int mi = 0; mi < 2; ++mi)
#pragma unroll
                for (int nj = 0; nj < 4; ++nj) {
                    float* cc = c[mi][half * 4 + nj];
                    mma_bf16(cc, ah[mi], bh[nj]);
                    mma_bf16(cc, ah[mi], bl[nj]);
                    mma_bf16(cc, al[mi], bh[nj]);
                }
        }

        if (ch + 1 < NCH) {
            const int nb = buf ^ 1;
            store_stage(nb, ra0, ra1, rb0, rb1);
            __syncthreads();
            buf = nb;
        }
    }

    // Epilogue: z==3 applies sigmoid(c + b_beta[col]).
#pragma unroll
    for (int mi = 0; mi < 2; ++mi) {
        const int r0 = m0 + wm * 32 + mi * 16 + g;
#pragma unroll
        for (int ni = 0; ni < 8; ++ni) {
            const int col = n0 + wn * 64 + ni * 8 + 2 * tig;
            float v0 = c[mi][ni][0], v1 = c[mi][ni][1];
            float v2 = c[mi][ni][2], v3 = c[mi][ni][3];
            if (z == 3) {
                const float bb0 = b_beta[col], bb1 = b_beta[col + 1];
                v0 = sigmoidf_acc(v0 + bb0);
                v1 = sigmoidf_acc(v1 + bb1);
                v2 = sigmoidf_acc(v2 + bb0);
                v3 = sigmoidf_acc(v3 + bb1);
            }
            float2* p0 = (float2*)&C[(size_t)r0 * HN + col];
            float2* p1 = (float2*)&C[(size_t)(r0 + 8) * HN + col];
            *p0 = make_float2(v0, v1);
            *p1 = make_float2(v2, v3);
        }
    }
}

// ---------------------------------------------------------------------------
// Fast device math
// ---------------------------------------------------------------------------
__device__ __forceinline__ float fast_ex2(float v) {
    float r;  asm("ex2.approx.f32 %0, %1;" : "=f"(r) : "f"(v));  return r;
}
__device__ __forceinline__ float fast_rcp(float v) {
    float r;  asm("rcp.approx.f32 %0, %1;" : "=f"(r) : "f"(v));  return r;
}
__device__ __forceinline__ float fast_sqrt(float v) {
    float r;  asm("sqrt.approx.f32 %0, %1;" : "=f"(r) : "f"(v));  return r;
}
__device__ __forceinline__ float fast_tanh(float x) {   // single MUFU.TANH
    float r;  asm("tanh.approx.f32 %0, %1;" : "=f"(r) : "f"(x));  return r;
}
__device__ __forceinline__ float fast_sigmoid(float x) {
    return fast_rcp(1.f + fast_ex2(x * -1.4426950408889634f));
}

// ---------------------------------------------------------------------------
// Barrier-free scan (R6 structure + tanh.approx). One CTA per (b,h); 16 warps;
// warp w owns rows 4w..4w+3; lane l: row 4w+(l>>3), cols (l&7)*8..+8.
// ---------------------------------------------------------------------------
__global__ __launch_bounds__(512, 1) void scan_kernel(
    const float* __restrict__ S0,
    float* __restrict__ out,
    float* __restrict__ Sfin)
{
    const int bh   = blockIdx.x;
    const int b    = bh >> 3;
    const int h    = bh & 7;
    const int tid  = threadIdx.x;
    const int w    = tid >> 5;
    const int lane = tid & 31;
    const int row  = w * 4 + (lane >> 3);
    const int jb   = (lane & 7) * 8;

    float S[8];
    const float* S0p = S0 + (size_t)bh * NDIM * NDIM + row * NDIM + jb;
#pragma unroll
    for (int e = 0; e < 8; ++e) S[e] = S0p[e];

    const size_t slab = (size_t)ROWS * HN;
    const size_t step = (size_t)BATCH * HN;
    const float* pk = g_proj + 0 * slab + (size_t)b * HN + h * NDIM;
    const float* pv = g_proj + 1 * slab + (size_t)b * HN + h * NDIM;
    const float* pq = g_proj + 2 * slab + (size_t)b * HN + h * NDIM;
    const float* pb = g_proj + 3 * slab + (size_t)b * HN + h * NDIM;

    float4 kc0 = *(const float4*)(pk + jb);
    float4 kc1 = *(const float4*)(pk + jb + 4);
    float4 qc0 = *(const float4*)(pq + jb);
    float4 qc1 = *(const float4*)(pq + jb + 4);
    float  vc  = pv[row];
    float  bc  = pb[row];

    float* outp = out + (size_t)b * HN + h * NDIM + row;

    for (int t = 0; t < T_STEPS; ++t) {
        float4 kp0, kp1, qp0, qp1;
        float  vp = 0.f, bp = 0.f;
        if (t + 1 < T_STEPS) {
            const size_t o = (size_t)(t + 1) * step;
            kp0 = *(const float4*)(pk + o + jb);
            kp1 = *(const float4*)(pk + o + jb + 4);
            qp0 = *(const float4*)(pq + o + jb);
            qp1 = *(const float4*)(pq + o + jb + 4);
            vp  = __ldg(pv + o + row);
            bp  = __ldg(pb + o + row);
        } else {
            kp0 = kc0; kp1 = kc1; qp0 = qc0; qp1 = qc1;
        }

        const float kv[8] = {kc0.x, kc0.y, kc0.z, kc0.w, kc1.x, kc1.y, kc1.z, kc1.w};

        float ss = 0.f, rr = 0.f;
#pragma unroll
        for (int e = 0; e < 8; ++e) {
            ss = fmaf(kv[e], kv[e], ss);
            rr = fmaf(S[e], kv[e], rr);
        }
        ss += __shfl_xor_sync(0xffffffffu, ss, 1);
        rr += __shfl_xor_sync(0xffffffffu, rr, 1);
        ss += __shfl_xor_sync(0xffffffffu, ss, 2);
        rr += __shfl_xor_sync(0xffffffffu, rr, 2);
        ss += __shfl_xor_sync(0xffffffffu, ss, 4);
        rr += __shfl_xor_sync(0xffffffffu, rr, 4);

        const float inv   = fast_rcp(fast_sqrt(ss) + 1e-6f);
        const float delta = vc - rr * inv;
        const float dinv  = delta * inv;
        const float beta  = bc;

        const float qv[8] = {qc0.x, qc0.y, qc0.z, qc0.w, qc1.x, qc1.y, qc1.z, qc1.w};

        float acc = 0.f;
#pragma unroll
        for (int e = 0; e < 8; ++e) {
            float s = fast_tanh(fmaf(dinv, kv[e], beta * S[e]));
            S[e] = s;
            acc = fmaf(s, qv[e], acc);
        }
        acc += __shfl_xor_sync(0xffffffffu, acc, 1);
        acc += __shfl_xor_sync(0xffffffffu, acc, 2);
        acc += __shfl_xor_sync(0xffffffffu, acc, 4);

        if ((lane & 7) == 0) {
            outp[(size_t)t * step] = acc * acc * fast_sigmoid(acc);
        }

        kc0 = kp0; kc1 = kp1; qc0 = qp0; qc1 = qp1; vc = vp; bc = bp;
    }

    if (Sfin != nullptr) {
        float* sp = Sfin + (size_t)bh * NDIM * NDIM + row * NDIM + jb;
#pragma unroll
        for (int e = 0; e < 8; ++e) sp[e] = S[e];
    }
}

// ---------------------------------------------------------------------------
// Inputs: x, S0, W_k, W_v, W_q, W_beta, b_beta
// ---------------------------------------------------------------------------
extern "C" void kernel_launch(void* const* d_in, const int* in_sizes, int n_in,
                              void* d_out, int out_size)
{
    const float* x   = (const float*)d_in[0];
    const float* S0  = (const float*)d_in[1];
    const float* Wk  = (const float*)d_in[2];
    const float* Wv  = (const float*)d_in[3];
    const float* Wq  = (const float*)d_in[4];
    const float* Wb  = (const float*)d_in[5];
    const float* bbt = (const float*)d_in[6];
    float* out = (float*)d_out;

    dim3 gg(HN / GBN, ROWS / GBM, 4);
    proj_gemm_bf16<<<gg, 256>>>(x, Wk, Wv, Wq, Wb, bbt);

    float* sfin = nullptr;
    if ((size_t)out_size >= OUT_MAIN + SFIN_ELEMS) sfin = out + OUT_MAIN;

    scan_kernel<<<BATCH * HEADS, 512>>>(S0, out, sfin);
}

// round 10
// speedup vs baseline: 2.2689x; 1.0941x over previous
#include <cuda_runtime.h>
#include <cuda_bf16.h>
#include <math.h>
#include <stdint.h>

// Problem constants
#define T_STEPS 1024
#define BATCH   16
#define DIMK    1024
#define HEADS   8
#define NDIM    64
#define HN      512                 // HEADS*NDIM
#define ROWS    (T_STEPS*BATCH)     // 16384
#define OUT_MAIN ((size_t)T_STEPS*BATCH*HN)        // 8388608
#define SFIN_ELEMS ((size_t)BATCH*HEADS*NDIM*NDIM) // 524288

// Scratch for the 4 projections (k,v,q,beta_sigmoided): 128 MB
__device__ float g_proj[4ull * ROWS * HN];

__device__ __forceinline__ float sigmoidf_acc(float v) {
    return 1.f / (1.f + expf(-v));
}

// ---------------------------------------------------------------------------
// bf16 split helpers: x = hi + lo (each bf16); 3-term mma recovers ~2^-18.
// Pairs packed along K: low 16 bits = even k, high 16 bits = odd k.
// ---------------------------------------------------------------------------
__device__ __forceinline__ void split_bf16_pair(float f0, float f1,
                                                uint32_t& hi, uint32_t& lo) {
    __nv_bfloat162 hp = __floats2bfloat162_rn(f0, f1);
    hi = *reinterpret_cast<uint32_t*>(&hp);
    float l0 = f0 - __low2float(hp);
    float l1 = f1 - __high2float(hp);
    __nv_bfloat162 lp = __floats2bfloat162_rn(l0, l1);
    lo = *reinterpret_cast<uint32_t*>(&lp);
}

__device__ __forceinline__ void mma_bf16(float c[4], const uint32_t a[4],
                                         const uint32_t b0, const uint32_t b1) {
    asm volatile(
        "mma.sync.aligned.m16n8k16.row.col.f32.bf16.bf16.f32 "
        "{%0,%1,%2,%3},{%4,%5,%6,%7},{%8,%9},{%0,%1,%2,%3};"
        : "+f"(c[0]), "+f"(c[1]), "+f"(c[2]), "+f"(c[3])
        : "r"(a[0]), "r"(a[1]), "r"(a[2]), "r"(a[3]), "r"(b0), "r"(b1));
}

__device__ __forceinline__ void ldm_x4(uint32_t r[4], uint32_t a) {
    asm volatile("ldmatrix.sync.aligned.m8n8.x4.shared.b16 {%0,%1,%2,%3}, [%4];"
                 : "=r"(r[0]), "=r"(r[1]), "=r"(r[2]), "=r"(r[3]) : "r"(a));
}

__device__ __forceinline__ uint32_t smem_u32(const void* p) {
    uint32_t a;
    asm("{ .reg .u64 t; cvta.to.shared.u64 t, %1; cvt.u32.u64 %0, t; }" : "=r"(a) : "l"(p));
    return a;
}

// 32B-row swizzle: XOR 16B-slot bits [4:5] with 128B-line bits [7:8].
#define SWZ(o) ((o) ^ ((((o) >> 7) & 3u) << 4))

// ---------------------------------------------------------------------------
// Projection GEMM: C[m,n] = sum_k x[m,k] * W[n,k], 3x bf16 split.
// CTA 128x128, K-chunk 16 floats; tiles stored row-major [row][8 u32] w/ swizzle.
// Fragments via ldmatrix.x4; staging via STS.128. 256 thr (4m x 2n warps), occ 2.
// grid = (HN/128, ROWS/128, 4). z==3 applies sigmoid(+b_beta) in epilogue.
// ---------------------------------------------------------------------------
#define GBM 128
#define GBN 128
#define KF  16
#define STAGE_B 16384   // 4 tiles * 4KB
#define TILE_B  4096

__global__ __launch_bounds__(256, 2) void proj_gemm_bf16(
    const float* __restrict__ x,
    const float* __restrict__ Wk, const float* __restrict__ Wv,
    const float* __restrict__ Wq, const float* __restrict__ Wb,
    const float* __restrict__ b_beta)
{
    __shared__ __align__(128) uint32_t SM[2 * 4 * 1024];  // 32 KB

    const int z = blockIdx.z;
    const float* __restrict__ W = (z == 0) ? Wk : (z == 1) ? Wv : (z == 2) ? Wq : Wb;
    float* __restrict__ C = g_proj + (size_t)z * ROWS * HN;

    const uint32_t smb = smem_u32(SM);

    const int tid  = threadIdx.x;
    const int lane = tid & 31;
    const int wid  = tid >> 5;
    const int wm   = wid >> 1;        // 0..3 -> 32 rows
    const int wn   = wid & 1;         // 0..1 -> 64 cols
    const int g    = lane >> 2;
    const int tig  = lane & 3;

    const int m0 = blockIdx.y * GBM;
    const int n0 = blockIdx.x * GBN;

    // Global loads: thread -> row lm (0..127), 8 floats at lkf (0 or 8)
    const int lm  = tid >> 1;
    const int lkf = (tid & 1) * 8;
    const float* xA = x + (size_t)(m0 + lm) * DIMK + lkf;
    const float* wB = W + (size_t)(n0 + lm) * DIMK + lkf;

    // Store address (within a tile): row lm, 16B half (tid&1)
    const uint32_t stOff = SWZ((uint32_t)(lm * 32 + (tid & 1) * 16));

    // ldmatrix lane-relative offsets
    const uint32_t aRel = (uint32_t)((lane & 15) * 32 + (lane >> 4) * 16);
    const uint32_t bRel = (uint32_t)((((lane & 7) + ((lane >> 4) << 3)) * 32)
                                     + (((lane >> 3) & 1) * 16));
    // tile-relative physical ldmatrix addresses (stage-invariant)
    uint32_t adrA[2], adrB[4];
#pragma unroll
    for (int mi = 0; mi < 2; ++mi)
        adrA[mi] = SWZ((uint32_t)((wm * 32 + mi * 16) * 32) + aRel);
#pragma unroll
    for (int p = 0; p < 4; ++p)
        adrB[p] = SWZ((uint32_t)((wn * 64 + p * 16) * 32) + bRel);

    float c[2][8][4];
#pragma unroll
    for (int mi = 0; mi < 2; ++mi)
#pragma unroll
        for (int ni = 0; ni < 8; ++ni)
#pragma unroll
            for (int e = 0; e < 4; ++e) c[mi][ni][e] = 0.f;

    float4 ra0 = *(const float4*)(xA);
    float4 ra1 = *(const float4*)(xA + 4);
    float4 rb0 = *(const float4*)(wB);
    float4 rb1 = *(const float4*)(wB + 4);

    // split + pack one chunk into stage s (tiles: 0=Ah 1=Al 2=Bh 3=Bl)
    auto store_stage = [&](int s, float4 a0, float4 a1, float4 b0, float4 b1) {
        const float fa[8] = {a0.x, a0.y, a0.z, a0.w, a1.x, a1.y, a1.z, a1.w};
        const float fb[8] = {b0.x, b0.y, b0.z, b0.w, b1.x, b1.y, b1.z, b1.w};
        uint32_t h[4], l[4];
        char* base = (char*)SM + s * STAGE_B + stOff;
#pragma unroll
        for (int j = 0; j < 4; ++j) split_bf16_pair(fa[2 * j], fa[2 * j + 1], h[j], l[j]);
        *(uint4*)(base + 0 * TILE_B) = make_uint4(h[0], h[1], h[2], h[3]);
        *(uint4*)(base + 1 * TILE_B) = make_uint4(l[0], l[1], l[2], l[3]);
#pragma unroll
        for (int j = 0; j < 4; ++j) split_bf16_pair(fb[2 * j], fb[2 * j + 1], h[j], l[j]);
        *(uint4*)(base + 2 * TILE_B) = make_uint4(h[0], h[1], h[2], h[3]);
        *(uint4*)(base + 3 * TILE_B) = make_uint4(l[0], l[1], l[2], l[3]);
    };

    store_stage(0, ra0, ra1, rb0, rb1);
    __syncthreads();

    const int NCH = DIMK / KF;   // 64
    int buf = 0;
    for (int ch = 0; ch < NCH; ++ch) {
        if (ch + 1 < NCH) {
            const size_t koff = (size_t)(ch + 1) * KF;
            ra0 = *(const float4*)(xA + koff);
            ra1 = *(const float4*)(xA + koff + 4);
            rb0 = *(const float4*)(wB + koff);
            rb1 = *(const float4*)(wB + koff + 4);
        }

        const uint32_t sOff = smb + buf * STAGE_B;

        uint32_t ah[2][4], al[2][4];
#pragma unroll
        for (int mi = 0; mi < 2; ++mi) {
            ldm_x4(ah[mi], sOff + 0 * TILE_B + adrA[mi]);
            ldm_x4(al[mi], sOff + 1 * TILE_B + adrA[mi]);
        }

#pragma unroll
        for (int p = 0; p < 4; ++p) {
            uint32_t bh[4], bl[4];
            ldm_x4(bh, sOff + 2 * TILE_B + adrB[p]);
            ldm_x4(bl, sOff + 3 * TILE_B + adrB[p]);
            // bh = {b0,b1 of nj=2p, b0,b1 of nj=2p+1}
#pragma unroll
            for (int mi = 0; mi < 2; ++mi)
#pragma unroll
                for (int j = 0; j < 2; ++j) {
                    float* cc = c[mi][2 * p + j];
                    mma_bf16(cc, ah[mi], bh[2 * j], bh[2 * j + 1]);
                    mma_bf16(cc, ah[mi], bl[2 * j], bl[2 * j + 1]);
                    mma_bf16(cc, al[mi], bh[2 * j], bh[2 * j + 1]);
                }
        }

        if (ch + 1 < NCH) {
            store_stage(buf ^ 1, ra0, ra1, rb0, rb1);
            __syncthreads();
            buf ^= 1;
        }
    }

    // Epilogue: z==3 applies sigmoid(c + b_beta[col]).
#pragma unroll
    for (int mi = 0; mi < 2; ++mi) {
        const int r0 = m0 + wm * 32 + mi * 16 + g;
#pragma unroll
        for (int ni = 0; ni < 8; ++ni) {
            const int col = n0 + wn * 64 + ni * 8 + 2 * tig;
            float v0 = c[mi][ni][0], v1 = c[mi][ni][1];
            float v2 = c[mi][ni][2], v3 = c[mi][ni][3];
            if (z == 3) {
                const float bb0 = b_beta[col], bb1 = b_beta[col + 1];
                v0 = sigmoidf_acc(v0 + bb0);
                v1 = sigmoidf_acc(v1 + bb1);
                v2 = sigmoidf_acc(v2 + bb0);
                v3 = sigmoidf_acc(v3 + bb1);
            }
            float2* p0 = (float2*)&C[(size_t)r0 * HN + col];
            float2* p1 = (float2*)&C[(size_t)(r0 + 8) * HN + col];
            *p0 = make_float2(v0, v1);
            *p1 = make_float2(v2, v3);
        }
    }
}

// ---------------------------------------------------------------------------
// Fast device math
// ---------------------------------------------------------------------------
__device__ __forceinline__ float fast_ex2(float v) {
    float r;  asm("ex2.approx.f32 %0, %1;" : "=f"(r) : "f"(v));  return r;
}
__device__ __forceinline__ float fast_rcp(float v) {
    float r;  asm("rcp.approx.f32 %0, %1;" : "=f"(r) : "f"(v));  return r;
}
__device__ __forceinline__ float fast_rsqrt(float v) {
    float r;  asm("rsqrt.approx.f32 %0, %1;" : "=f"(r) : "f"(v));  return r;
}
__device__ __forceinline__ float fast_tanh(float x) {   // single MUFU.TANH
    float r;  asm("tanh.approx.f32 %0, %1;" : "=f"(r) : "f"(x));  return r;
}
__device__ __forceinline__ float fast_sigmoid(float x) {
    return fast_rcp(1.f + fast_ex2(x * -1.4426950408889634f));
}

// ---------------------------------------------------------------------------
// Barrier-free scan, pipelined norm. One CTA per (b,h); 16 warps; warp w owns
// rows 4w..4w+3; lane l: row 4w+(l>>3), cols (l&7)*8..+8. inv(t+1) = rsqrt of
// k(t+1) norm, computed at the END of step t (k(t+1) prefetched) so step t+1's
// critical path is rr-reduce -> delta -> tanh only.
// ---------------------------------------------------------------------------
__global__ __launch_bounds__(512, 1) void scan_kernel(
    const float* __restrict__ S0,
    float* __restrict__ out,
    float* __restrict__ Sfin)
{
    const int bh   = blockIdx.x;
    const int b    = bh >> 3;
    const int h    = bh & 7;
    const int tid  = threadIdx.x;
    const int w    = tid >> 5;
    const int lane = tid & 31;
    const int row  = w * 4 + (lane >> 3);
    const int jb   = (lane & 7) * 8;

    float S[8];
    const float* S0p = S0 + (size_t)bh * NDIM * NDIM + row * NDIM + jb;
#pragma unroll
    for (int e = 0; e < 8; ++e) S[e] = S0p[e];

    const size_t slab = (size_t)ROWS * HN;
    const size_t step = (size_t)BATCH * HN;
    const float* pk = g_proj + 0 * slab + (size_t)b * HN + h * NDIM;
    const float* pv = g_proj + 1 * slab + (size_t)b * HN + h * NDIM;
    const float* pq = g_proj + 2 * slab + (size_t)b * HN + h * NDIM;
    const float* pb = g_proj + 3 * slab + (size_t)b * HN + h * NDIM;

    float4 kc0 = *(const float4*)(pk + jb);
    float4 kc1 = *(const float4*)(pk + jb + 4);
    float4 qc0 = *(const float4*)(pq + jb);
    float4 qc1 = *(const float4*)(pq + jb + 4);
    float  vc  = pv[row];
    float  bc  = pb[row];

    // inv for step 0
    float invc;
    {
        float ss = kc0.x * kc0.x + kc0.y * kc0.y + kc0.z * kc0.z + kc0.w * kc0.w
                 + kc1.x * kc1.x + kc1.y * kc1.y + kc1.z * kc1.z + kc1.w * kc1.w;
        ss += __shfl_xor_sync(0xffffffffu, ss, 1);
        ss += __shfl_xor_sync(0xffffffffu, ss, 2);
        ss += __shfl_xor_sync(0xffffffffu, ss, 4);
        invc = fast_rsqrt(ss + 1e-12f);
    }

    float* outp = out + (size_t)b * HN + h * NDIM + row;

    for (int t = 0; t < T_STEPS; ++t) {
        float4 kp0, kp1, qp0, qp1;
        float  vp = 0.f, bp = 0.f;
        if (t + 1 < T_STEPS) {
            const size_t o = (size_t)(t + 1) * step;
            kp0 = *(const float4*)(pk + o + jb);
            kp1 = *(const float4*)(pk + o + jb + 4);
            qp0 = *(const float4*)(pq + o + jb);
            qp1 = *(const float4*)(pq + o + jb + 4);
            vp  = __ldg(pv + o + row);
            bp  = __ldg(pb + o + row);
        } else {
            kp0 = kc0; kp1 = kc1; qp0 = qc0; qp1 = qc1;
        }

        const float kv[8] = {kc0.x, kc0.y, kc0.z, kc0.w, kc1.x, kc1.y, kc1.z, kc1.w};

        // rr = S_row . k  (two-accumulator chain, 8-lane row-group reduce)
        float r0 = 0.f, r1 = 0.f;
#pragma unroll
        for (int e = 0; e < 4; ++e) {
            r0 = fmaf(S[e], kv[e], r0);
            r1 = fmaf(S[e + 4], kv[e + 4], r1);
        }
        float rr = r0 + r1;
        rr += __shfl_xor_sync(0xffffffffu, rr, 1);
        rr += __shfl_xor_sync(0xffffffffu, rr, 2);
        rr += __shfl_xor_sync(0xffffffffu, rr, 4);

        const float delta = vc - rr * invc;
        const float dinv  = delta * invc;
        const float beta  = bc;

        const float qv[8] = {qc0.x, qc0.y, qc0.z, qc0.w, qc1.x, qc1.y, qc1.z, qc1.w};

        float acc = 0.f;
#pragma unroll
        for (int e = 0; e < 8; ++e) {
            float s = fast_tanh(fmaf(dinv, kv[e], beta * S[e]));
            S[e] = s;
            acc = fmaf(s, qv[e], acc);
        }
        acc += __shfl_xor_sync(0xffffffffu, acc, 1);
        acc += __shfl_xor_sync(0xffffffffu, acc, 2);
        acc += __shfl_xor_sync(0xffffffffu, acc, 4);

        if ((lane & 7) == 0) {
            outp[(size_t)t * step] = acc * acc * fast_sigmoid(acc);
        }

        // next step's inv (off critical path: only needs k(t+1))
        float ss = kp0.x * kp0.x + kp0.y * kp0.y + kp0.z * kp0.z + kp0.w * kp0.w
                 + kp1.x * kp1.x + kp1.y * kp1.y + kp1.z * kp1.z + kp1.w * kp1.w;
        ss += __shfl_xor_sync(0xffffffffu, ss, 1);
        ss += __shfl_xor_sync(0xffffffffu, ss, 2);
        ss += __shfl_xor_sync(0xffffffffu, ss, 4);
        invc = fast_rsqrt(ss + 1e-12f);

        kc0 = kp0; kc1 = kp1; qc0 = qp0; qc1 = qp1; vc = vp; bc = bp;
    }

    if (Sfin != nullptr) {
        float* sp = Sfin + (size_t)bh * NDIM * NDIM + row * NDIM + jb;
#pragma unroll
        for (int e = 0; e < 8; ++e) sp[e] = S[e];
    }
}

// ---------------------------------------------------------------------------
// Inputs: x, S0, W_k, W_v, W_q, W_beta, b_beta
// ---------------------------------------------------------------------------
extern "C" void kernel_launch(void* const* d_in, const int* in_sizes, int n_in,
                              void* d_out, int out_size)
{
    const float* x   = (const float*)d_in[0];
    const float* S0  = (const float*)d_in[1];
    const float* Wk  = (const float*)d_in[2];
    const float* Wv  = (const float*)d_in[3];
    const float* Wq  = (const float*)d_in[4];
    const float* Wb  = (const float*)d_in[5];
    const float* bbt = (const float*)d_in[6];
    float* out = (float*)d_out;

    dim3 gg(HN / GBN, ROWS / GBM, 4);
    proj_gemm_bf16<<<gg, 256>>>(x, Wk, Wv, Wq, Wb, bbt);

    float* sfin = nullptr;
    if ((size_t)out_size >= OUT_MAIN + SFIN_ELEMS) sfin = out + OUT_MAIN;

    scan_kernel<<<BATCH * HEADS, 512>>>(S0, out, sfin);
}

// round 11
// speedup vs baseline: 2.2723x; 1.0015x over previous
#include <cuda_runtime.h>
#include <cuda_bf16.h>
#include <math.h>
#include <stdint.h>

// Problem constants
#define T_STEPS 1024
#define BATCH   16
#define DIMK    1024
#define HEADS   8
#define NDIM    64
#define HN      512                 // HEADS*NDIM
#define ROWS    (T_STEPS*BATCH)     // 16384
#define OUT_MAIN ((size_t)T_STEPS*BATCH*HN)        // 8388608
#define SFIN_ELEMS ((size_t)BATCH*HEADS*NDIM*NDIM) // 524288

// Scratch for the 4 projections (k,v,q,beta_sigmoided): 128 MB
__device__ float g_proj[4ull * ROWS * HN];

__device__ __forceinline__ float sigmoidf_acc(float v) {
    return 1.f / (1.f + expf(-v));
}

// ---------------------------------------------------------------------------
// bf16 split helpers: x = hi + lo (each bf16); 3-term mma recovers ~2^-18.
// Pairs packed along K: low 16 bits = even k, high 16 bits = odd k.
// ---------------------------------------------------------------------------
__device__ __forceinline__ void split_bf16_pair(float f0, float f1,
                                                uint32_t& hi, uint32_t& lo) {
    __nv_bfloat162 hp = __floats2bfloat162_rn(f0, f1);
    hi = *reinterpret_cast<uint32_t*>(&hp);
    float l0 = f0 - __low2float(hp);
    float l1 = f1 - __high2float(hp);
    __nv_bfloat162 lp = __floats2bfloat162_rn(l0, l1);
    lo = *reinterpret_cast<uint32_t*>(&lp);
}

__device__ __forceinline__ void mma_bf16(float c[4], const uint32_t a[4],
                                         const uint32_t b0, const uint32_t b1) {
    asm volatile(
        "mma.sync.aligned.m16n8k16.row.col.f32.bf16.bf16.f32 "
        "{%0,%1,%2,%3},{%4,%5,%6,%7},{%8,%9},{%0,%1,%2,%3};"
        : "+f"(c[0]), "+f"(c[1]), "+f"(c[2]), "+f"(c[3])
        : "r"(a[0]), "r"(a[1]), "r"(a[2]), "r"(a[3]), "r"(b0), "r"(b1));
}

__device__ __forceinline__ void ldm_x4(uint32_t r[4], uint32_t a) {
    asm volatile("ldmatrix.sync.aligned.m8n8.x4.shared.b16 {%0,%1,%2,%3}, [%4];"
                 : "=r"(r[0]), "=r"(r[1]), "=r"(r[2]), "=r"(r[3]) : "r"(a));
}

__device__ __forceinline__ uint32_t smem_u32(const void* p) {
    uint32_t a;
    asm("{ .reg .u64 t; cvta.to.shared.u64 t, %1; cvt.u32.u64 %0, t; }" : "=r"(a) : "l"(p));
    return a;
}

// 32B-row swizzle: XOR 16B-slot bits [4:5] with 128B-line bits [7:8].
#define SWZ(o) ((o) ^ ((((o) >> 7) & 3u) << 4))

// ---------------------------------------------------------------------------
// Projection GEMM (unchanged from R10, 608us): C = x @ W^T, 3x bf16 split,
// ldmatrix fragments, STS.128 staging, CTA 128x128, 256 thr, occ 2.
// ---------------------------------------------------------------------------
#define GBM 128
#define GBN 128
#define KF  16
#define STAGE_B 16384   // 4 tiles * 4KB
#define TILE_B  4096

__global__ __launch_bounds__(256, 2) void proj_gemm_bf16(
    const float* __restrict__ x,
    const float* __restrict__ Wk, const float* __restrict__ Wv,
    const float* __restrict__ Wq, const float* __restrict__ Wb,
    const float* __restrict__ b_beta)
{
    __shared__ __align__(128) uint32_t SM[2 * 4 * 1024];  // 32 KB

    const int z = blockIdx.z;
    const float* __restrict__ W = (z == 0) ? Wk : (z == 1) ? Wv : (z == 2) ? Wq : Wb;
    float* __restrict__ C = g_proj + (size_t)z * ROWS * HN;

    const uint32_t smb = smem_u32(SM);

    const int tid  = threadIdx.x;
    const int lane = tid & 31;
    const int wid  = tid >> 5;
    const int wm   = wid >> 1;
    const int wn   = wid & 1;
    const int g    = lane >> 2;
    const int tig  = lane & 3;

    const int m0 = blockIdx.y * GBM;
    const int n0 = blockIdx.x * GBN;

    const int lm  = tid >> 1;
    const int lkf = (tid & 1) * 8;
    const float* xA = x + (size_t)(m0 + lm) * DIMK + lkf;
    const float* wB = W + (size_t)(n0 + lm) * DIMK + lkf;

    const uint32_t stOff = SWZ((uint32_t)(lm * 32 + (tid & 1) * 16));

    const uint32_t aRel = (uint32_t)((lane & 15) * 32 + (lane >> 4) * 16);
    const uint32_t bRel = (uint32_t)((((lane & 7) + ((lane >> 4) << 3)) * 32)
                                     + (((lane >> 3) & 1) * 16));
    uint32_t adrA[2], adrB[4];
#pragma unroll
    for (int mi = 0; mi < 2; ++mi)
        adrA[mi] = SWZ((uint32_t)((wm * 32 + mi * 16) * 32) + aRel);
#pragma unroll
    for (int p = 0; p < 4; ++p)
        adrB[p] = SWZ((uint32_t)((wn * 64 + p * 16) * 32) + bRel);

    float c[2][8][4];
#pragma unroll
    for (int mi = 0; mi < 2; ++mi)
#pragma unroll
        for (int ni = 0; ni < 8; ++ni)
#pragma unroll
            for (int e = 0; e < 4; ++e) c[mi][ni][e] = 0.f;

    float4 ra0 = *(const float4*)(xA);
    float4 ra1 = *(const float4*)(xA + 4);
    float4 rb0 = *(const float4*)(wB);
    float4 rb1 = *(const float4*)(wB + 4);

    auto store_stage = [&](int s, float4 a0, float4 a1, float4 b0, float4 b1) {
        const float fa[8] = {a0.x, a0.y, a0.z, a0.w, a1.x, a1.y, a1.z, a1.w};
        const float fb[8] = {b0.x, b0.y, b0.z, b0.w, b1.x, b1.y, b1.z, b1.w};
        uint32_t h[4], l[4];
        char* base = (char*)SM + s * STAGE_B + stOff;
#pragma unroll
        for (int j = 0; j < 4; ++j) split_bf16_pair(fa[2 * j], fa[2 * j + 1], h[j], l[j]);
        *(uint4*)(base + 0 * TILE_B) = make_uint4(h[0], h[1], h[2], h[3]);
        *(uint4*)(base + 1 * TILE_B) = make_uint4(l[0], l[1], l[2], l[3]);
#pragma unroll
        for (int j = 0; j < 4; ++j) split_bf16_pair(fb[2 * j], fb[2 * j + 1], h[j], l[j]);
        *(uint4*)(base + 2 * TILE_B) = make_uint4(h[0], h[1], h[2], h[3]);
        *(uint4*)(base + 3 * TILE_B) = make_uint4(l[0], l[1], l[2], l[3]);
    };

    store_stage(0, ra0, ra1, rb0, rb1);
    __syncthreads();

    const int NCH = DIMK / KF;   // 64
    int buf = 0;
    for (int ch = 0; ch < NCH; ++ch) {
        if (ch + 1 < NCH) {
            const size_t koff = (size_t)(ch + 1) * KF;
            ra0 = *(const float4*)(xA + koff);
            ra1 = *(const float4*)(xA + koff + 4);
            rb0 = *(const float4*)(wB + koff);
            rb1 = *(const float4*)(wB + koff + 4);
        }

        const uint32_t sOff = smb + buf * STAGE_B;

        uint32_t ah[2][4], al[2][4];
#pragma unroll
        for (int mi = 0; mi < 2; ++mi) {
            ldm_x4(ah[mi], sOff + 0 * TILE_B + adrA[mi]);
            ldm_x4(al[mi], sOff + 1 * TILE_B + adrA[mi]);
        }

#pragma unroll
        for (int p = 0; p < 4; ++p) {
            uint32_t bh[4], bl[4];
            ldm_x4(bh, sOff + 2 * TILE_B + adrB[p]);
            ldm_x4(bl, sOff + 3 * TILE_B + adrB[p]);
#pragma unroll
            for (int mi = 0; mi < 2; ++mi)
#pragma unroll
                for (int j = 0; j < 2; ++j) {
                    float* cc = c[mi][2 * p + j];
                    mma_bf16(cc, ah[mi], bh[2 * j], bh[2 * j + 1]);
                    mma_bf16(cc, ah[mi], bl[2 * j], bl[2 * j + 1]);
                    mma_bf16(cc, al[mi], bh[2 * j], bh[2 * j + 1]);
                }
        }

        if (ch + 1 < NCH) {
            store_stage(buf ^ 1, ra0, ra1, rb0, rb1);
            __syncthreads();
            buf ^= 1;
        }
    }

#pragma unroll
    for (int mi = 0; mi < 2; ++mi) {
        const int r0 = m0 + wm * 32 + mi * 16 + g;
#pragma unroll
        for (int ni = 0; ni < 8; ++ni) {
            const int col = n0 + wn * 64 + ni * 8 + 2 * tig;
            float v0 = c[mi][ni][0], v1 = c[mi][ni][1];
            float v2 = c[mi][ni][2], v3 = c[mi][ni][3];
            if (z == 3) {
                const float bb0 = b_beta[col], bb1 = b_beta[col + 1];
                v0 = sigmoidf_acc(v0 + bb0);
                v1 = sigmoidf_acc(v1 + bb1);
                v2 = sigmoidf_acc(v2 + bb0);
                v3 = sigmoidf_acc(v3 + bb1);
            }
            float2* p0 = (float2*)&C[(size_t)r0 * HN + col];
            float2* p1 = (float2*)&C[(size_t)(r0 + 8) * HN + col];
            *p0 = make_float2(v0, v1);
            *p1 = make_float2(v2, v3);
        }
    }
}

// ---------------------------------------------------------------------------
// Fast device math
// ---------------------------------------------------------------------------
__device__ __forceinline__ float fast_ex2(float v) {
    float r;  asm("ex2.approx.f32 %0, %1;" : "=f"(r) : "f"(v));  return r;
}
__device__ __forceinline__ float fast_rcp(float v) {
    float r;  asm("rcp.approx.f32 %0, %1;" : "=f"(r) : "f"(v));  return r;
}
__device__ __forceinline__ float fast_rsqrt(float v) {
    float r;  asm("rsqrt.approx.f32 %0, %1;" : "=f"(r) : "f"(v));  return r;
}
__device__ __forceinline__ float fast_tanh(float x) {   // single MUFU.TANH
    float r;  asm("tanh.approx.f32 %0, %1;" : "=f"(r) : "f"(x));  return r;
}
__device__ __forceinline__ float fast_sigmoid(float x) {
    return fast_rcp(1.f + fast_ex2(x * -1.4426950408889634f));
}

// ---------------------------------------------------------------------------
// Barrier-free scan, unroll x2 register ping-pong. One CTA per (b,h); 16
// warps; warp w owns rows 4w..4w+3; lane l: row 4w+(l>>3), cols (l&7)*8..+8.
// R9 ordering restored: ss+rr merged interleaved reduce on CURRENT k (loads
// are consumed a full step after issue -> latency hidden). A/B input buffers
// alternate, eliminating the per-step register copies.
// ---------------------------------------------------------------------------
__global__ __launch_bounds__(512, 1) void scan_kernel(
    const float* __restrict__ S0,
    float* __restrict__ out,
    float* __restrict__ Sfin)
{
    const int bh   = blockIdx.x;
    const int b    = bh >> 3;
    const int h    = bh & 7;
    const int tid  = threadIdx.x;
    const int w    = tid >> 5;
    const int lane = tid & 31;
    const int row  = w * 4 + (lane >> 3);
    const int jb   = (lane & 7) * 8;

    float S[8];
    const float* S0p = S0 + (size_t)bh * NDIM * NDIM + row * NDIM + jb;
#pragma unroll
    for (int e = 0; e < 8; ++e) S[e] = S0p[e];

    const size_t slab = (size_t)ROWS * HN;
    const size_t step = (size_t)BATCH * HN;
    const float* pk = g_proj + 0 * slab + (size_t)b * HN + h * NDIM;
    const float* pv = g_proj + 1 * slab + (size_t)b * HN + h * NDIM;
    const float* pq = g_proj + 2 * slab + (size_t)b * HN + h * NDIM;
    const float* pb = g_proj + 3 * slab + (size_t)b * HN + h * NDIM;

    float* outp = out + (size_t)b * HN + h * NDIM + row;

    // One step of the recurrence at time t using the given inputs.
    auto do_step = [&](const float4& k0, const float4& k1,
                       const float4& q0, const float4& q1,
                       float vv, float bb, int t) {
        const float kv[8] = {k0.x, k0.y, k0.z, k0.w, k1.x, k1.y, k1.z, k1.w};

        float ss = 0.f, rr = 0.f;
#pragma unroll
        for (int e = 0; e < 8; ++e) {
            ss = fmaf(kv[e], kv[e], ss);
            rr = fmaf(S[e], kv[e], rr);
        }
        ss += __shfl_xor_sync(0xffffffffu, ss, 1);
        rr += __shfl_xor_sync(0xffffffffu, rr, 1);
        ss += __shfl_xor_sync(0xffffffffu, ss, 2);
        rr += __shfl_xor_sync(0xffffffffu, rr, 2);
        ss += __shfl_xor_sync(0xffffffffu, ss, 4);
        rr += __shfl_xor_sync(0xffffffffu, rr, 4);

        const float inv   = fast_rsqrt(ss + 1e-12f);
        const float delta = vv - rr * inv;
        const float dinv  = delta * inv;

        const float qv[8] = {q0.x, q0.y, q0.z, q0.w, q1.x, q1.y, q1.z, q1.w};

        float acc = 0.f;
#pragma unroll
        for (int e = 0; e < 8; ++e) {
            float s = fast_tanh(fmaf(dinv, kv[e], bb * S[e]));
            S[e] = s;
            acc = fmaf(s, qv[e], acc);
        }
        acc += __shfl_xor_sync(0xffffffffu, acc, 1);
        acc += __shfl_xor_sync(0xffffffffu, acc, 2);
        acc += __shfl_xor_sync(0xffffffffu, acc, 4);

        if ((lane & 7) == 0) {
            outp[(size_t)t * step] = acc * acc * fast_sigmoid(acc);
        }
    };

    // Buffer A: step t inputs.  Buffer B: step t+1 inputs.
    float4 kA0 = *(const float4*)(pk + jb);
    float4 kA1 = *(const float4*)(pk + jb + 4);
    float4 qA0 = *(const float4*)(pq + jb);
    float4 qA1 = *(const float4*)(pq + jb + 4);
    float  vA  = pv[row];
    float  bA  = pb[row];
    float4 kB0, kB1, qB0, qB1;
    float  vB, bB;

    for (int t = 0; t < T_STEPS; t += 2) {
        // prefetch t+1 into B (t+1 <= 1023 always; T_STEPS even)
        {
            const size_t o = (size_t)(t + 1) * step;
            kB0 = *(const float4*)(pk + o + jb);
            kB1 = *(const float4*)(pk + o + jb + 4);
            qB0 = *(const float4*)(pq + o + jb);
            qB1 = *(const float4*)(pq + o + jb + 4);
            vB  = __ldg(pv + o + row);
            bB  = __ldg(pb + o + row);
        }

        do_step(kA0, kA1, qA0, qA1, vA, bA, t);

        // prefetch t+2 into A
        if (t + 2 < T_STEPS) {
            const size_t o = (size_t)(t + 2) * step;
            kA0 = *(const float4*)(pk + o + jb);
            kA1 = *(const float4*)(pk + o + jb + 4);
            qA0 = *(const float4*)(pq + o + jb);
            qA1 = *(const float4*)(pq + o + jb + 4);
            vA  = __ldg(pv + o + row);
            bA  = __ldg(pb + o + row);
        }

        do_step(kB0, kB1, qB0, qB1, vB, bB, t + 1);
    }

    if (Sfin != nullptr) {
        float* sp = Sfin + (size_t)bh * NDIM * NDIM + row * NDIM + jb;
#pragma unroll
        for (int e = 0; e < 8; ++e) sp[e] = S[e];
    }
}

// ---------------------------------------------------------------------------
// Inputs: x, S0, W_k, W_v, W_q, W_beta, b_beta
// ---------------------------------------------------------------------------
extern "C" void kernel_launch(void* const* d_in, const int* in_sizes, int n_in,
                              void* d_out, int out_size)
{
    const float* x   = (const float*)d_in[0];
    const float* S0  = (const float*)d_in[1];
    const float* Wk  = (const float*)d_in[2];
    const float* Wv  = (const float*)d_in[3];
    const float* Wq  = (const float*)d_in[4];
    const float* Wb  = (const float*)d_in[5];
    const float* bbt = (const float*)d_in[6];
    float* out = (float*)d_out;

    dim3 gg(HN / GBN, ROWS / GBM, 4);
    proj_gemm_bf16<<<gg, 256>>>(x, Wk, Wv, Wq, Wb, bbt);

    float* sfin = nullptr;
    if ((size_t)out_size >= OUT_MAIN + SFIN_ELEMS) sfin = out + OUT_MAIN;

    scan_kernel<<<BATCH * HEADS, 512>>>(S0, out, sfin);
}

// round 12
// speedup vs baseline: 2.4567x; 1.0812x over previous
#include <cuda_runtime.h>
#include <cuda_bf16.h>
#include <math.h>
#include <stdint.h>

// Problem constants
#define T_STEPS 1024
#define BATCH   16
#define DIMK    1024
#define HEADS   8
#define NDIM    64
#define HN      512                 // HEADS*NDIM
#define ROWS    (T_STEPS*BATCH)     // 16384
#define OUT_MAIN ((size_t)T_STEPS*BATCH*HN)        // 8388608
#define SFIN_ELEMS ((size_t)BATCH*HEADS*NDIM*NDIM) // 524288

// Scratch for the 4 projections (k,v,q,beta_sigmoided): 128 MB
__device__ float g_proj[4ull * ROWS * HN];

__device__ __forceinline__ float sigmoidf_acc(float v) {
    return 1.f / (1.f + expf(-v));
}

// ---------------------------------------------------------------------------
// bf16 split helpers: x = hi + lo (each bf16); 3-term mma recovers ~2^-18.
// Pairs packed along K: low 16 bits = even k, high 16 bits = odd k.
// ---------------------------------------------------------------------------
__device__ __forceinline__ void split_bf16_pair(float f0, float f1,
                                                uint32_t& hi, uint32_t& lo) {
    __nv_bfloat162 hp = __floats2bfloat162_rn(f0, f1);
    hi = *reinterpret_cast<uint32_t*>(&hp);
    float l0 = f0 - __low2float(hp);
    float l1 = f1 - __high2float(hp);
    __nv_bfloat162 lp = __floats2bfloat162_rn(l0, l1);
    lo = *reinterpret_cast<uint32_t*>(&lp);
}

__device__ __forceinline__ void mma_bf16(float c[4], const uint32_t a[4],
                                         const uint32_t b0, const uint32_t b1) {
    asm volatile(
        "mma.sync.aligned.m16n8k16.row.col.f32.bf16.bf16.f32 "
        "{%0,%1,%2,%3},{%4,%5,%6,%7},{%8,%9},{%0,%1,%2,%3};"
        : "+f"(c[0]), "+f"(c[1]), "+f"(c[2]), "+f"(c[3])
        : "r"(a[0]), "r"(a[1]), "r"(a[2]), "r"(a[3]), "r"(b0), "r"(b1));
}

__device__ __forceinline__ void ldm_x4(uint32_t r[4], uint32_t a) {
    asm volatile("ldmatrix.sync.aligned.m8n8.x4.shared.b16 {%0,%1,%2,%3}, [%4];"
                 : "=r"(r[0]), "=r"(r[1]), "=r"(r[2]), "=r"(r[3]) : "r"(a));
}

__device__ __forceinline__ uint32_t smem_u32(const void* p) {
    uint32_t a;
    asm("{ .reg .u64 t; cvta.to.shared.u64 t, %1; cvt.u32.u64 %0, t; }" : "=r"(a) : "l"(p));
    return a;
}

// 32B-row swizzle: XOR 16B-slot bits [4:5] with 128B-line bits [7:8].
#define SWZ(o) ((o) ^ ((((o) >> 7) & 3u) << 4))

// ---------------------------------------------------------------------------
// Projection GEMM (unchanged, 608us): C = x @ W^T, 3x bf16 split,
// ldmatrix fragments, STS.128 staging, CTA 128x128, 256 thr, occ 2.
// ---------------------------------------------------------------------------
#define GBM 128
#define GBN 128
#define KF  16
#define STAGE_B 16384   // 4 tiles * 4KB
#define TILE_B  4096

__global__ __launch_bounds__(256, 2) void proj_gemm_bf16(
    const float* __restrict__ x,
    const float* __restrict__ Wk, const float* __restrict__ Wv,
    const float* __restrict__ Wq, const float* __restrict__ Wb,
    const float* __restrict__ b_beta)
{
    __shared__ __align__(128) uint32_t SM[2 * 4 * 1024];  // 32 KB

    const int z = blockIdx.z;
    const float* __restrict__ W = (z == 0) ? Wk : (z == 1) ? Wv : (z == 2) ? Wq : Wb;
    float* __restrict__ C = g_proj + (size_t)z * ROWS * HN;

    const uint32_t smb = smem_u32(SM);

    const int tid  = threadIdx.x;
    const int lane = tid & 31;
    const int wid  = tid >> 5;
    const int wm   = wid >> 1;
    const int wn   = wid & 1;
    const int g    = lane >> 2;
    const int tig  = lane & 3;

    const int m0 = blockIdx.y * GBM;
    const int n0 = blockIdx.x * GBN;

    const int lm  = tid >> 1;
    const int lkf = (tid & 1) * 8;
    const float* xA = x + (size_t)(m0 + lm) * DIMK + lkf;
    const float* wB = W + (size_t)(n0 + lm) * DIMK + lkf;

    const uint32_t stOff = SWZ((uint32_t)(lm * 32 + (tid & 1) * 16));

    const uint32_t aRel = (uint32_t)((lane & 15) * 32 + (lane >> 4) * 16);
    const uint32_t bRel = (uint32_t)((((lane & 7) + ((lane >> 4) << 3)) * 32)
                                     + (((lane >> 3) & 1) * 16));
    uint32_t adrA[2], adrB[4];
#pragma unroll
    for (int mi = 0; mi < 2; ++mi)
        adrA[mi] = SWZ((uint32_t)((wm * 32 + mi * 16) * 32) + aRel);
#pragma unroll
    for (int p = 0; p < 4; ++p)
        adrB[p] = SWZ((uint32_t)((wn * 64 + p * 16) * 32) + bRel);

    float c[2][8][4];
#pragma unroll
    for (int mi = 0; mi < 2; ++mi)
#pragma unroll
        for (int ni = 0; ni < 8; ++ni)
#pragma unroll
            for (int e = 0; e < 4; ++e) c[mi][ni][e] = 0.f;

    float4 ra0 = *(const float4*)(xA);
    float4 ra1 = *(const float4*)(xA + 4);
    float4 rb0 = *(const float4*)(wB);
    float4 rb1 = *(const float4*)(wB + 4);

    auto store_stage = [&](int s, float4 a0, float4 a1, float4 b0, float4 b1) {
        const float fa[8] = {a0.x, a0.y, a0.z, a0.w, a1.x, a1.y, a1.z, a1.w};
        const float fb[8] = {b0.x, b0.y, b0.z, b0.w, b1.x, b1.y, b1.z, b1.w};
        uint32_t h[4], l[4];
        char* base = (char*)SM + s * STAGE_B + stOff;
#pragma unroll
        for (int j = 0; j < 4; ++j) split_bf16_pair(fa[2 * j], fa[2 * j + 1], h[j], l[j]);
        *(uint4*)(base + 0 * TILE_B) = make_uint4(h[0], h[1], h[2], h[3]);
        *(uint4*)(base + 1 * TILE_B) = make_uint4(l[0], l[1], l[2], l[3]);
#pragma unroll
        for (int j = 0; j < 4; ++j) split_bf16_pair(fb[2 * j], fb[2 * j + 1], h[j], l[j]);
        *(uint4*)(base + 2 * TILE_B) = make_uint4(h[0], h[1], h[2], h[3]);
        *(uint4*)(base + 3 * TILE_B) = make_uint4(l[0], l[1], l[2], l[3]);
    };

    store_stage(0, ra0, ra1, rb0, rb1);
    __syncthreads();

    const int NCH = DIMK / KF;   // 64
    int buf = 0;
    for (int ch = 0; ch < NCH; ++ch) {
        if (ch + 1 < NCH) {
            const size_t koff = (size_t)(ch + 1) * KF;
            ra0 = *(const float4*)(xA + koff);
            ra1 = *(const float4*)(xA + koff + 4);
            rb0 = *(const float4*)(wB + koff);
            rb1 = *(const float4*)(wB + koff + 4);
        }

        const uint32_t sOff = smb + buf * STAGE_B;

        uint32_t ah[2][4], al[2][4];
#pragma unroll
        for (int mi = 0; mi < 2; ++mi) {
            ldm_x4(ah[mi], sOff + 0 * TILE_B + adrA[mi]);
            ldm_x4(al[mi], sOff + 1 * TILE_B + adrA[mi]);
        }

#pragma unroll
        for (int p = 0; p < 4; ++p) {
            uint32_t bh[4], bl[4];
            ldm_x4(bh, sOff + 2 * TILE_B + adrB[p]);
            ldm_x4(bl, sOff + 3 * TILE_B + adrB[p]);
#pragma unroll
            for (int mi = 0; mi < 2; ++mi)
#pragma unroll
                for (int j = 0; j < 2; ++j) {
                    float* cc = c[mi][2 * p + j];
                    mma_bf16(cc, ah[mi], bh[2 * j], bh[2 * j + 1]);
                    mma_bf16(cc, ah[mi], bl[2 * j], bl[2 * j + 1]);
                    mma_bf16(cc, al[mi], bh[2 * j], bh[2 * j + 1]);
                }
        }

        if (ch + 1 < NCH) {
            store_stage(buf ^ 1, ra0, ra1, rb0, rb1);
            __syncthreads();
            buf ^= 1;
        }
    }

#pragma unroll
    for (int mi = 0; mi < 2; ++mi) {
        const int r0 = m0 + wm * 32 + mi * 16 + g;
#pragma unroll
        for (int ni = 0; ni < 8; ++ni) {
            const int col = n0 + wn * 64 + ni * 8 + 2 * tig;
            float v0 = c[mi][ni][0], v1 = c[mi][ni][1];
            float v2 = c[mi][ni][2], v3 = c[mi][ni][3];
            if (z == 3) {
                const float bb0 = b_beta[col], bb1 = b_beta[col + 1];
                v0 = sigmoidf_acc(v0 + bb0);
                v1 = sigmoidf_acc(v1 + bb1);
                v2 = sigmoidf_acc(v2 + bb0);
                v3 = sigmoidf_acc(v3 + bb1);
            }
            float2* p0 = (float2*)&C[(size_t)r0 * HN + col];
            float2* p1 = (float2*)&C[(size_t)(r0 + 8) * HN + col];
            *p0 = make_float2(v0, v1);
            *p1 = make_float2(v2, v3);
        }
    }
}

// ---------------------------------------------------------------------------
// Fast device math
// ---------------------------------------------------------------------------
__device__ __forceinline__ float fast_ex2(float v) {
    float r;  asm("ex2.approx.f32 %0, %1;" : "=f"(r) : "f"(v));  return r;
}
__device__ __forceinline__ float fast_rcp(float v) {
    float r;  asm("rcp.approx.f32 %0, %1;" : "=f"(r) : "f"(v));  return r;
}
__device__ __forceinline__ float fast_rsqrt(float v) {
    float r;  asm("rsqrt.approx.f32 %0, %1;" : "=f"(r) : "f"(v));  return r;
}
__device__ __forceinline__ float fast_tanh(float x) {   // single MUFU.TANH
    float r;  asm("tanh.approx.f32 %0, %1;" : "=f"(r) : "f"(x));  return r;
}
__device__ __forceinline__ float fast_sigmoid(float x) {
    return fast_rcp(1.f + fast_ex2(x * -1.4426950408889634f));
}

// ---------------------------------------------------------------------------
// normalize_k: k <- k / ||k|| per (row, head). One block per row (16384),
// 256 threads; warp w handles head w (cols 64w..64w+63), lane holds float2.
// ---------------------------------------------------------------------------
__global__ __launch_bounds__(256, 8) void normalize_k()
{
    float* pk = g_proj;   // slab 0
    const int rowi = blockIdx.x;
    const int wid  = threadIdx.x >> 5;     // head
    const int lane = threadIdx.x & 31;

    float2* p = (float2*)(pk + (size_t)rowi * HN + wid * NDIM + lane * 2);
    float2 kk = *p;
    float ss = kk.x * kk.x + kk.y * kk.y;
#pragma unroll
    for (int o = 16; o > 0; o >>= 1)
        ss += __shfl_xor_sync(0xffffffffu, ss, o);
    const float inv = fast_rsqrt(ss + 1e-12f);
    kk.x *= inv;  kk.y *= inv;
    *p = kk;
}

// ---------------------------------------------------------------------------
// Barrier-free scan (R9 loop shape, k pre-normalized). One CTA per (b,h);
// 16 warps; warp w owns rows 4w..4w+3; lane l: row 4w+(l>>3), cols (l&7)*8.
// Per-step chain: rr-reduce -> delta -> tanh -> acc-reduce. No norm work.
// ---------------------------------------------------------------------------
__global__ __launch_bounds__(512, 1) void scan_kernel(
    const float* __restrict__ S0,
    float* __restrict__ out,
    float* __restrict__ Sfin)
{
    const int bh   = blockIdx.x;
    const int b    = bh >> 3;
    const int h    = bh & 7;
    const int tid  = threadIdx.x;
    const int w    = tid >> 5;
    const int lane = tid & 31;
    const int row  = w * 4 + (lane >> 3);
    const int jb   = (lane & 7) * 8;

    float S[8];
    const float* S0p = S0 + (size_t)bh * NDIM * NDIM + row * NDIM + jb;
#pragma unroll
    for (int e = 0; e < 8; ++e) S[e] = S0p[e];

    const size_t slab = (size_t)ROWS * HN;
    const size_t step = (size_t)BATCH * HN;
    const float* pk = g_proj + 0 * slab + (size_t)b * HN + h * NDIM;   // normalized
    const float* pv = g_proj + 1 * slab + (size_t)b * HN + h * NDIM;
    const float* pq = g_proj + 2 * slab + (size_t)b * HN + h * NDIM;
    const float* pb = g_proj + 3 * slab + (size_t)b * HN + h * NDIM;

    float4 kc0 = *(const float4*)(pk + jb);
    float4 kc1 = *(const float4*)(pk + jb + 4);
    float4 qc0 = *(const float4*)(pq + jb);
    float4 qc1 = *(const float4*)(pq + jb + 4);
    float  vc  = pv[row];
    float  bc  = pb[row];

    float* outp = out + (size_t)b * HN + h * NDIM + row;

    for (int t = 0; t < T_STEPS; ++t) {
        float4 kp0, kp1, qp0, qp1;
        float  vp = 0.f, bp = 0.f;
        if (t + 1 < T_STEPS) {
            const size_t o = (size_t)(t + 1) * step;
            kp0 = *(const float4*)(pk + o + jb);
            kp1 = *(const float4*)(pk + o + jb + 4);
            qp0 = *(const float4*)(pq + o + jb);
            qp1 = *(const float4*)(pq + o + jb + 4);
            vp  = __ldg(pv + o + row);
            bp  = __ldg(pb + o + row);
        } else {
            kp0 = kc0; kp1 = kc1; qp0 = qc0; qp1 = qc1;
        }

        const float kv[8] = {kc0.x, kc0.y, kc0.z, kc0.w, kc1.x, kc1.y, kc1.z, kc1.w};

        // rr = S_row . k_norm  (two-accumulator chain, 8-lane reduce)
        float r0 = 0.f, r1 = 0.f;
#pragma unroll
        for (int e = 0; e < 4; ++e) {
            r0 = fmaf(S[e], kv[e], r0);
            r1 = fmaf(S[e + 4], kv[e + 4], r1);
        }
        float rr = r0 + r1;
        rr += __shfl_xor_sync(0xffffffffu, rr, 1);
        rr += __shfl_xor_sync(0xffffffffu, rr, 2);
        rr += __shfl_xor_sync(0xffffffffu, rr, 4);

        const float delta = vc - rr;      // k already unit-norm
        const float beta  = bc;

        const float qv[8] = {qc0.x, qc0.y, qc0.z, qc0.w, qc1.x, qc1.y, qc1.z, qc1.w};

        float acc = 0.f;
#pragma unroll
        for (int e = 0; e < 8; ++e) {
            float s = fast_tanh(fmaf(delta, kv[e], beta * S[e]));
            S[e] = s;
            acc = fmaf(s, qv[e], acc);
        }
        acc += __shfl_xor_sync(0xffffffffu, acc, 1);
        acc += __shfl_xor_sync(0xffffffffu, acc, 2);
        acc += __shfl_xor_sync(0xffffffffu, acc, 4);

        if ((lane & 7) == 0) {
            outp[(size_t)t * step] = acc * acc * fast_sigmoid(acc);
        }

        kc0 = kp0; kc1 = kp1; qc0 = qp0; qc1 = qp1; vc = vp; bc = bp;
    }

    if (Sfin != nullptr) {
        float* sp = Sfin + (size_t)bh * NDIM * NDIM + row * NDIM + jb;
#pragma unroll
        for (int e = 0; e < 8; ++e) sp[e] = S[e];
    }
}

// ---------------------------------------------------------------------------
// Inputs: x, S0, W_k, W_v, W_q, W_beta, b_beta
// ---------------------------------------------------------------------------
extern "C" void kernel_launch(void* const* d_in, const int* in_sizes, int n_in,
                              void* d_out, int out_size)
{
    const float* x   = (const float*)d_in[0];
    const float* S0  = (const float*)d_in[1];
    const float* Wk  = (const float*)d_in[2];
    const float* Wv  = (const float*)d_in[3];
    const float* Wq  = (const float*)d_in[4];
    const float* Wb  = (const float*)d_in[5];
    const float* bbt = (const float*)d_in[6];
    float* out = (float*)d_out;

    dim3 gg(HN / GBN, ROWS / GBM, 4);
    proj_gemm_bf16<<<gg, 256>>>(x, Wk, Wv, Wq, Wb, bbt);

    normalize_k<<<ROWS, 256>>>();

    float* sfin = nullptr;
    if ((size_t)out_size >= OUT_MAIN + SFIN_ELEMS) sfin = out + OUT_MAIN;

    scan_kernel<<<BATCH * HEADS, 512>>>(S0, out, sfin);
}

// round 13
// speedup vs baseline: 2.4893x; 1.0133x over previous
#include <cuda_runtime.h>
#include <cuda_bf16.h>
#include <math.h>
#include <stdint.h>

// Problem constants
#define T_STEPS 1024
#define BATCH   16
#define DIMK    1024
#define HEADS   8
#define NDIM    64
#define HN      512                 // HEADS*NDIM
#define ROWS    (T_STEPS*BATCH)     // 16384
#define OUT_MAIN ((size_t)T_STEPS*BATCH*HN)        // 8388608
#define SFIN_ELEMS ((size_t)BATCH*HEADS*NDIM*NDIM) // 524288

// Scratch for the 4 projections (k,v,q,beta_sigmoided): 128 MB
__device__ float g_proj[4ull * ROWS * HN];

__device__ __forceinline__ float sigmoidf_acc(float v) {
    return 1.f / (1.f + expf(-v));
}

// ---------------------------------------------------------------------------
// bf16 split helpers: x = hi + lo (each bf16); 3-term mma recovers ~2^-18.
// Pairs packed along K: low 16 bits = even k, high 16 bits = odd k.
// ---------------------------------------------------------------------------
__device__ __forceinline__ void split_bf16_pair(float f0, float f1,
                                                uint32_t& hi, uint32_t& lo) {
    __nv_bfloat162 hp = __floats2bfloat162_rn(f0, f1);
    hi = *reinterpret_cast<uint32_t*>(&hp);
    float l0 = f0 - __low2float(hp);
    float l1 = f1 - __high2float(hp);
    __nv_bfloat162 lp = __floats2bfloat162_rn(l0, l1);
    lo = *reinterpret_cast<uint32_t*>(&lp);
}

__device__ __forceinline__ void mma_bf16(float c[4], const uint32_t a[4],
                                         const uint32_t b0, const uint32_t b1) {
    asm volatile(
        "mma.sync.aligned.m16n8k16.row.col.f32.bf16.bf16.f32 "
        "{%0,%1,%2,%3},{%4,%5,%6,%7},{%8,%9},{%0,%1,%2,%3};"
        : "+f"(c[0]), "+f"(c[1]), "+f"(c[2]), "+f"(c[3])
        : "r"(a[0]), "r"(a[1]), "r"(a[2]), "r"(a[3]), "r"(b0), "r"(b1));
}

__device__ __forceinline__ void ldm_x4(uint32_t r[4], uint32_t a) {
    asm volatile("ldmatrix.sync.aligned.m8n8.x4.shared.b16 {%0,%1,%2,%3}, [%4];"
                 : "=r"(r[0]), "=r"(r[1]), "=r"(r[2]), "=r"(r[3]) : "r"(a));
}

__device__ __forceinline__ uint32_t smem_u32(const void* p) {
    uint32_t a;
    asm("{ .reg .u64 t; cvta.to.shared.u64 t, %1; cvt.u32.u64 %0, t; }" : "=r"(a) : "l"(p));
    return a;
}

// 32B-row swizzle: XOR 16B-slot bits [4:5] with 128B-line bits [7:8].
#define SWZ(o) ((o) ^ ((((o) >> 7) & 3u) << 4))

// ---------------------------------------------------------------------------
// Projection GEMM (unchanged, ~630us, tensor 61% / L1 85%): C = x @ W^T,
// 3x bf16 split, ldmatrix fragments, STS.128 staging, CTA 128x128, occ 2.
// ---------------------------------------------------------------------------
#define GBM 128
#define GBN 128
#define KF  16
#define STAGE_B 16384   // 4 tiles * 4KB
#define TILE_B  4096

__global__ __launch_bounds__(256, 2) void proj_gemm_bf16(
    const float* __restrict__ x,
    const float* __restrict__ Wk, const float* __restrict__ Wv,
    const float* __restrict__ Wq, const float* __restrict__ Wb,
    const float* __restrict__ b_beta)
{
    __shared__ __align__(128) uint32_t SM[2 * 4 * 1024];  // 32 KB

    const int z = blockIdx.z;
    const float* __restrict__ W = (z == 0) ? Wk : (z == 1) ? Wv : (z == 2) ? Wq : Wb;
    float* __restrict__ C = g_proj + (size_t)z * ROWS * HN;

    const uint32_t smb = smem_u32(SM);

    const int tid  = threadIdx.x;
    const int lane = tid & 31;
    const int wid  = tid >> 5;
    const int wm   = wid >> 1;
    const int wn   = wid & 1;
    const int g    = lane >> 2;
    const int tig  = lane & 3;

    const int m0 = blockIdx.y * GBM;
    const int n0 = blockIdx.x * GBN;

    const int lm  = tid >> 1;
    const int lkf = (tid & 1) * 8;
    const float* xA = x + (size_t)(m0 + lm) * DIMK + lkf;
    const float* wB = W + (size_t)(n0 + lm) * DIMK + lkf;

    const uint32_t stOff = SWZ((uint32_t)(lm * 32 + (tid & 1) * 16));

    const uint32_t aRel = (uint32_t)((lane & 15) * 32 + (lane >> 4) * 16);
    const uint32_t bRel = (uint32_t)((((lane & 7) + ((lane >> 4) << 3)) * 32)
                                     + (((lane >> 3) & 1) * 16));
    uint32_t adrA[2], adrB[4];
#pragma unroll
    for (int mi = 0; mi < 2; ++mi)
        adrA[mi] = SWZ((uint32_t)((wm * 32 + mi * 16) * 32) + aRel);
#pragma unroll
    for (int p = 0; p < 4; ++p)
        adrB[p] = SWZ((uint32_t)((wn * 64 + p * 16) * 32) + bRel);

    float c[2][8][4];
#pragma unroll
    for (int mi = 0; mi < 2; ++mi)
#pragma unroll
        for (int ni = 0; ni < 8; ++ni)
#pragma unroll
            for (int e = 0; e < 4; ++e) c[mi][ni][e] = 0.f;

    float4 ra0 = *(const float4*)(xA);
    float4 ra1 = *(const float4*)(xA + 4);
    float4 rb0 = *(const float4*)(wB);
    float4 rb1 = *(const float4*)(wB + 4);

    auto store_stage = [&](int s, float4 a0, float4 a1, float4 b0, float4 b1) {
        const float fa[8] = {a0.x, a0.y, a0.z, a0.w, a1.x, a1.y, a1.z, a1.w};
        const float fb[8] = {b0.x, b0.y, b0.z, b0.w, b1.x, b1.y, b1.z, b1.w};
        uint32_t h[4], l[4];
        char* base = (char*)SM + s * STAGE_B + stOff;
#pragma unroll
        for (int j = 0; j < 4; ++j) split_bf16_pair(fa[2 * j], fa[2 * j + 1], h[j], l[j]);
        *(uint4*)(base + 0 * TILE_B) = make_uint4(h[0], h[1], h[2], h[3]);
        *(uint4*)(base + 1 * TILE_B) = make_uint4(l[0], l[1], l[2], l[3]);
#pragma unroll
        for (int j = 0; j < 4; ++j) split_bf16_pair(fb[2 * j], fb[2 * j + 1], h[j], l[j]);
        *(uint4*)(base + 2 * TILE_B) = make_uint4(h[0], h[1], h[2], h[3]);
        *(uint4*)(base + 3 * TILE_B) = make_uint4(l[0], l[1], l[2], l[3]);
    };

    store_stage(0, ra0, ra1, rb0, rb1);
    __syncthreads();

    const int NCH = DIMK / KF;   // 64
    int buf = 0;
    for (int ch = 0; ch < NCH; ++ch) {
        if (ch + 1 < NCH) {
            const size_t koff = (size_t)(ch + 1) * KF;
            ra0 = *(const float4*)(xA + koff);
            ra1 = *(const float4*)(xA + koff + 4);
            rb0 = *(const float4*)(wB + koff);
            rb1 = *(const float4*)(wB + koff + 4);
        }

        const uint32_t sOff = smb + buf * STAGE_B;

        uint32_t ah[2][4], al[2][4];
#pragma unroll
        for (int mi = 0; mi < 2; ++mi) {
            ldm_x4(ah[mi], sOff + 0 * TILE_B + adrA[mi]);
            ldm_x4(al[mi], sOff + 1 * TILE_B + adrA[mi]);
        }

#pragma unroll
        for (int p = 0; p < 4; ++p) {
            uint32_t bh[4], bl[4];
            ldm_x4(bh, sOff + 2 * TILE_B + adrB[p]);
            ldm_x4(bl, sOff + 3 * TILE_B + adrB[p]);
#pragma unroll
            for (int mi = 0; mi < 2; ++mi)
#pragma unroll
                for (int j = 0; j < 2; ++j) {
                    float* cc = c[mi][2 * p + j];
                    mma_bf16(cc, ah[mi], bh[2 * j], bh[2 * j + 1]);
                    mma_bf16(cc, ah[mi], bl[2 * j], bl[2 * j + 1]);
                    mma_bf16(cc, al[mi], bh[2 * j], bh[2 * j + 1]);
                }
        }

        if (ch + 1 < NCH) {
            store_stage(buf ^ 1, ra0, ra1, rb0, rb1);
            __syncthreads();
            buf ^= 1;
        }
    }

#pragma unroll
    for (int mi = 0; mi < 2; ++mi) {
        const int r0 = m0 + wm * 32 + mi * 16 + g;
#pragma unroll
        for (int ni = 0; ni < 8; ++ni) {
            const int col = n0 + wn * 64 + ni * 8 + 2 * tig;
            float v0 = c[mi][ni][0], v1 = c[mi][ni][1];
            float v2 = c[mi][ni][2], v3 = c[mi][ni][3];
            if (z == 3) {
                const float bb0 = b_beta[col], bb1 = b_beta[col + 1];
                v0 = sigmoidf_acc(v0 + bb0);
                v1 = sigmoidf_acc(v1 + bb1);
                v2 = sigmoidf_acc(v2 + bb0);
                v3 = sigmoidf_acc(v3 + bb1);
            }
            float2* p0 = (float2*)&C[(size_t)r0 * HN + col];
            float2* p1 = (float2*)&C[(size_t)(r0 + 8) * HN + col];
            *p0 = make_float2(v0, v1);
            *p1 = make_float2(v2, v3);
        }
    }
}

// ---------------------------------------------------------------------------
// Fast device math
// ---------------------------------------------------------------------------
__device__ __forceinline__ float fast_ex2(float v) {
    float r;  asm("ex2.approx.f32 %0, %1;" : "=f"(r) : "f"(v));  return r;
}
__device__ __forceinline__ float fast_rcp(float v) {
    float r;  asm("rcp.approx.f32 %0, %1;" : "=f"(r) : "f"(v));  return r;
}
__device__ __forceinline__ float fast_rsqrt(float v) {
    float r;  asm("rsqrt.approx.f32 %0, %1;" : "=f"(r) : "f"(v));  return r;
}
__device__ __forceinline__ float fast_tanh(float x) {   // single MUFU.TANH
    float r;  asm("tanh.approx.f32 %0, %1;" : "=f"(r) : "f"(x));  return r;
}
__device__ __forceinline__ float fast_sigmoid(float x) {
    return fast_rcp(1.f + fast_ex2(x * -1.4426950408889634f));
}

// ---------------------------------------------------------------------------
// normalize_k: k <- k / ||k|| per (row, head). One block per row (16384),
// 256 threads; warp w handles head w, lane holds float2.
// ---------------------------------------------------------------------------
__global__ __launch_bounds__(256, 8) void normalize_k()
{
    float* pk = g_proj;   // slab 0
    const int rowi = blockIdx.x;
    const int wid  = threadIdx.x >> 5;     // head
    const int lane = threadIdx.x & 31;

    float2* p = (float2*)(pk + (size_t)rowi * HN + wid * NDIM + lane * 2);
    float2 kk = *p;
    float ss = kk.x * kk.x + kk.y * kk.y;
#pragma unroll
    for (int o = 16; o > 0; o >>= 1)
        ss += __shfl_xor_sync(0xffffffffu, ss, o);
    const float inv = fast_rsqrt(ss + 1e-12f);
    kk.x *= inv;  kk.y *= inv;
    *p = kk;
}

// ---------------------------------------------------------------------------
// Barrier-free scan, PREFETCH DISTANCE 2. One CTA per (b,h); 16 warps; warp w
// owns rows 4w..4w+3; lane l: row 4w+(l>>3), cols (l&7)*8..+8. Step t issues
// loads for t+2 (two chain-lengths of cover for the ~600cyc DRAM latency),
// consumes buffer C, rotates C<-N1<-N2. Step body identical to R12.
// ---------------------------------------------------------------------------
struct StepIn {
    float4 k0, k1, q0, q1;
    float  v, b;
};

__global__ __launch_bounds__(512, 1) void scan_kernel(
    const float* __restrict__ S0,
    float* __restrict__ out,
    float* __restrict__ Sfin)
{
    const int bh   = blockIdx.x;
    const int b    = bh >> 3;
    const int h    = bh & 7;
    const int tid  = threadIdx.x;
    const int w    = tid >> 5;
    const int lane = tid & 31;
    const int row  = w * 4 + (lane >> 3);
    const int jb   = (lane & 7) * 8;

    float S[8];
    const float* S0p = S0 + (size_t)bh * NDIM * NDIM + row * NDIM + jb;
#pragma unroll
    for (int e = 0; e < 8; ++e) S[e] = S0p[e];

    const size_t slab = (size_t)ROWS * HN;
    const size_t step = (size_t)BATCH * HN;
    const float* pk = g_proj + 0 * slab + (size_t)b * HN + h * NDIM;   // normalized
    const float* pv = g_proj + 1 * slab + (size_t)b * HN + h * NDIM;
    const float* pq = g_proj + 2 * slab + (size_t)b * HN + h * NDIM;
    const float* pb = g_proj + 3 * slab + (size_t)b * HN + h * NDIM;

    auto load_in = [&](int t) {
        StepIn r;
        const size_t o = (size_t)t * step;
        r.k0 = *(const float4*)(pk + o + jb);
        r.k1 = *(const float4*)(pk + o + jb + 4);
        r.q0 = *(const float4*)(pq + o + jb);
        r.q1 = *(const float4*)(pq + o + jb + 4);
        r.v  = __ldg(pv + o + row);
        r.b  = __ldg(pb + o + row);
        return r;
    };

    float* outp = out + (size_t)b * HN + h * NDIM + row;

    StepIn C  = load_in(0);
    StepIn N1 = load_in(1);
    StepIn N2;

    for (int t = 0; t < T_STEPS; ++t) {
        if (t + 2 < T_STEPS) N2 = load_in(t + 2);

        const float kv[8] = {C.k0.x, C.k0.y, C.k0.z, C.k0.w,
                             C.k1.x, C.k1.y, C.k1.z, C.k1.w};

        // rr = S_row . k_norm  (two-accumulator chain, 8-lane reduce)
        float r0 = 0.f, r1 = 0.f;
#pragma unroll
        for (int e = 0; e < 4; ++e) {
            r0 = fmaf(S[e], kv[e], r0);
            r1 = fmaf(S[e + 4], kv[e + 4], r1);
        }
        float rr = r0 + r1;
        rr += __shfl_xor_sync(0xffffffffu, rr, 1);
        rr += __shfl_xor_sync(0xffffffffu, rr, 2);
        rr += __shfl_xor_sync(0xffffffffu, rr, 4);

        const float delta = C.v - rr;      // k already unit-norm
        const float beta  = C.b;

        const float qv[8] = {C.q0.x, C.q0.y, C.q0.z, C.q0.w,
                             C.q1.x, C.q1.y, C.q1.z, C.q1.w};

        float acc = 0.f;
#pragma unroll
        for (int e = 0; e < 8; ++e) {
            float s = fast_tanh(fmaf(delta, kv[e], beta * S[e]));
            S[e] = s;
            acc = fmaf(s, qv[e], acc);
        }
        acc += __shfl_xor_sync(0xffffffffu, acc, 1);
        acc += __shfl_xor_sync(0xffffffffu, acc, 2);
        acc += __shfl_xor_sync(0xffffffffu, acc, 4);

        if ((lane & 7) == 0) {
            outp[(size_t)t * step] = acc * acc * fast_sigmoid(acc);
        }

        C = N1;
        N1 = N2;
    }

    if (Sfin != nullptr) {
        float* sp = Sfin + (size_t)bh * NDIM * NDIM + row * NDIM + jb;
#pragma unroll
        for (int e = 0; e < 8; ++e) sp[e] = S[e];
    }
}

// ---------------------------------------------------------------------------
// Inputs: x, S0, W_k, W_v, W_q, W_beta, b_beta
// ---------------------------------------------------------------------------
extern "C" void kernel_launch(void* const* d_in, const int* in_sizes, int n_in,
                              void* d_out, int out_size)
{
    const float* x   = (const float*)d_in[0];
    const float* S0  = (const float*)d_in[1];
    const float* Wk  = (const float*)d_in[2];
    const float* Wv  = (const float*)d_in[3];
    const float* Wq  = (const float*)d_in[4];
    const float* Wb  = (const float*)d_in[5];
    const float* bbt = (const float*)d_in[6];
    float* out = (float*)d_out;

    dim3 gg(HN / GBN, ROWS / GBM, 4);
    proj_gemm_bf16<<<gg, 256>>>(x, Wk, Wv, Wq, Wb, bbt);

    normalize_k<<<ROWS, 256>>>();

    float* sfin = nullptr;
    if ((size_t)out_size >= OUT_MAIN + SFIN_ELEMS) sfin = out + OUT_MAIN;

    scan_kernel<<<BATCH * HEADS, 512>>>(S0, out, sfin);
}

// round 14
// speedup vs baseline: 2.6459x; 1.0629x over previous
#include <cuda_runtime.h>
#include <cuda_bf16.h>
#include <math.h>
#include <stdint.h>

// Problem constants
#define T_STEPS 1024
#define BATCH   16
#define DIMK    1024
#define HEADS   8
#define NDIM    64
#define HN      512                 // HEADS*NDIM
#define ROWS    (T_STEPS*BATCH)     // 16384
#define OUT_MAIN ((size_t)T_STEPS*BATCH*HN)        // 8388608
#define SFIN_ELEMS ((size_t)BATCH*HEADS*NDIM*NDIM) // 524288

// Scratch for the 4 projections (k,v,q,beta_sigmoided): 128 MB
__device__ float g_proj[4ull * ROWS * HN];

__device__ __forceinline__ float sigmoidf_acc(float v) {
    return 1.f / (1.f + expf(-v));
}

// ---------------------------------------------------------------------------
// bf16 split helpers: x = hi + lo (each bf16); 3-term mma recovers ~2^-18.
// Pairs packed along K: low 16 bits = even k, high 16 bits = odd k.
// ---------------------------------------------------------------------------
__device__ __forceinline__ void split_bf16_pair(float f0, float f1,
                                                uint32_t& hi, uint32_t& lo) {
    __nv_bfloat162 hp = __floats2bfloat162_rn(f0, f1);
    hi = *reinterpret_cast<uint32_t*>(&hp);
    float l0 = f0 - __low2float(hp);
    float l1 = f1 - __high2float(hp);
    __nv_bfloat162 lp = __floats2bfloat162_rn(l0, l1);
    lo = *reinterpret_cast<uint32_t*>(&lp);
}

__device__ __forceinline__ void mma_bf16(float c[4], const uint32_t a[4],
                                         const uint32_t b0, const uint32_t b1) {
    asm volatile(
        "mma.sync.aligned.m16n8k16.row.col.f32.bf16.bf16.f32 "
        "{%0,%1,%2,%3},{%4,%5,%6,%7},{%8,%9},{%0,%1,%2,%3};"
        : "+f"(c[0]), "+f"(c[1]), "+f"(c[2]), "+f"(c[3])
        : "r"(a[0]), "r"(a[1]), "r"(a[2]), "r"(a[3]), "r"(b0), "r"(b1));
}

__device__ __forceinline__ void ldm_x4(uint32_t r[4], uint32_t a) {
    asm volatile("ldmatrix.sync.aligned.m8n8.x4.shared.b16 {%0,%1,%2,%3}, [%4];"
                 : "=r"(r[0]), "=r"(r[1]), "=r"(r[2]), "=r"(r[3]) : "r"(a));
}

__device__ __forceinline__ uint32_t smem_u32(const void* p) {
    uint32_t a;
    asm("{ .reg .u64 t; cvta.to.shared.u64 t, %1; cvt.u32.u64 %0, t; }" : "=r"(a) : "l"(p));
    return a;
}

// 32B-row swizzle: XOR 16B-slot bits [4:5] with 128B-line bits [7:8].
#define SWZ(o) ((o) ^ ((((o) >> 7) & 3u) << 4))

// ---------------------------------------------------------------------------
// Projection GEMM (frozen, ~632us, tensor 61% / L1 85%): C = x @ W^T,
// 3x bf16 split, ldmatrix fragments, STS.128 staging, CTA 128x128, occ 2.
// ---------------------------------------------------------------------------
#define GBM 128
#define GBN 128
#define KF  16
#define STAGE_B 16384   // 4 tiles * 4KB
#define TILE_B  4096

__global__ __launch_bounds__(256, 2) void proj_gemm_bf16(
    const float* __restrict__ x,
    const float* __restrict__ Wk, const float* __restrict__ Wv,
    const float* __restrict__ Wq, const float* __restrict__ Wb,
    const float* __restrict__ b_beta)
{
    __shared__ __align__(128) uint32_t SM[2 * 4 * 1024];  // 32 KB

    const int z = blockIdx.z;
    const float* __restrict__ W = (z == 0) ? Wk : (z == 1) ? Wv : (z == 2) ? Wq : Wb;
    float* __restrict__ C = g_proj + (size_t)z * ROWS * HN;

    const uint32_t smb = smem_u32(SM);

    const int tid  = threadIdx.x;
    const int lane = tid & 31;
    const int wid  = tid >> 5;
    const int wm   = wid >> 1;
    const int wn   = wid & 1;
    const int g    = lane >> 2;
    const int tig  = lane & 3;

    const int m0 = blockIdx.y * GBM;
    const int n0 = blockIdx.x * GBN;

    const int lm  = tid >> 1;
    const int lkf = (tid & 1) * 8;
    const float* xA = x + (size_t)(m0 + lm) * DIMK + lkf;
    const float* wB = W + (size_t)(n0 + lm) * DIMK + lkf;

    const uint32_t stOff = SWZ((uint32_t)(lm * 32 + (tid & 1) * 16));

    const uint32_t aRel = (uint32_t)((lane & 15) * 32 + (lane >> 4) * 16);
    const uint32_t bRel = (uint32_t)((((lane & 7) + ((lane >> 4) << 3)) * 32)
                                     + (((lane >> 3) & 1) * 16));
    uint32_t adrA[2], adrB[4];
#pragma unroll
    for (int mi = 0; mi < 2; ++mi)
        adrA[mi] = SWZ((uint32_t)((wm * 32 + mi * 16) * 32) + aRel);
#pragma unroll
    for (int p = 0; p < 4; ++p)
        adrB[p] = SWZ((uint32_t)((wn * 64 + p * 16) * 32) + bRel);

    float c[2][8][4];
#pragma unroll
    for (int mi = 0; mi < 2; ++mi)
#pragma unroll
        for (int ni = 0; ni < 8; ++ni)
#pragma unroll
            for (int e = 0; e < 4; ++e) c[mi][ni][e] = 0.f;

    float4 ra0 = *(const float4*)(xA);
    float4 ra1 = *(const float4*)(xA + 4);
    float4 rb0 = *(const float4*)(wB);
    float4 rb1 = *(const float4*)(wB + 4);

    auto store_stage = [&](int s, float4 a0, float4 a1, float4 b0, float4 b1) {
        const float fa[8] = {a0.x, a0.y, a0.z, a0.w, a1.x, a1.y, a1.z, a1.w};
        const float fb[8] = {b0.x, b0.y, b0.z, b0.w, b1.x, b1.y, b1.z, b1.w};
        uint32_t h[4], l[4];
        char* base = (char*)SM + s * STAGE_B + stOff;
#pragma unroll
        for (int j = 0; j < 4; ++j) split_bf16_pair(fa[2 * j], fa[2 * j + 1], h[j], l[j]);
        *(uint4*)(base + 0 * TILE_B) = make_uint4(h[0], h[1], h[2], h[3]);
        *(uint4*)(base + 1 * TILE_B) = make_uint4(l[0], l[1], l[2], l[3]);
#pragma unroll
        for (int j = 0; j < 4; ++j) split_bf16_pair(fb[2 * j], fb[2 * j + 1], h[j], l[j]);
        *(uint4*)(base + 2 * TILE_B) = make_uint4(h[0], h[1], h[2], h[3]);
        *(uint4*)(base + 3 * TILE_B) = make_uint4(l[0], l[1], l[2], l[3]);
    };

    store_stage(0, ra0, ra1, rb0, rb1);
    __syncthreads();

    const int NCH = DIMK / KF;   // 64
    int buf = 0;
    for (int ch = 0; ch < NCH; ++ch) {
        if (ch + 1 < NCH) {
            const size_t koff = (size_t)(ch + 1) * KF;
            ra0 = *(const float4*)(xA + koff);
            ra1 = *(const float4*)(xA + koff + 4);
            rb0 = *(const float4*)(wB + koff);
            rb1 = *(const float4*)(wB + koff + 4);
        }

        const uint32_t sOff = smb + buf * STAGE_B;

        uint32_t ah[2][4], al[2][4];
#pragma unroll
        for (int mi = 0; mi < 2; ++mi) {
            ldm_x4(ah[mi], sOff + 0 * TILE_B + adrA[mi]);
            ldm_x4(al[mi], sOff + 1 * TILE_B + adrA[mi]);
        }

#pragma unroll
        for (int p = 0; p < 4; ++p) {
            uint32_t bh[4], bl[4];
            ldm_x4(bh, sOff + 2 * TILE_B + adrB[p]);
            ldm_x4(bl, sOff + 3 * TILE_B + adrB[p]);
#pragma unroll
            for (int mi = 0; mi < 2; ++mi)
#pragma unroll
                for (int j = 0; j < 2; ++j) {
                    float* cc = c[mi][2 * p + j];
                    mma_bf16(cc, ah[mi], bh[2 * j], bh[2 * j + 1]);
                    mma_bf16(cc, ah[mi], bl[2 * j], bl[2 * j + 1]);
                    mma_bf16(cc, al[mi], bh[2 * j], bh[2 * j + 1]);
                }
        }

        if (ch + 1 < NCH) {
            store_stage(buf ^ 1, ra0, ra1, rb0, rb1);
            __syncthreads();
            buf ^= 1;
        }
    }

#pragma unroll
    for (int mi = 0; mi < 2; ++mi) {
        const int r0 = m0 + wm * 32 + mi * 16 + g;
#pragma unroll
        for (int ni = 0; ni < 8; ++ni) {
            const int col = n0 + wn * 64 + ni * 8 + 2 * tig;
            float v0 = c[mi][ni][0], v1 = c[mi][ni][1];
            float v2 = c[mi][ni][2], v3 = c[mi][ni][3];
            if (z == 3) {
                const float bb0 = b_beta[col], bb1 = b_beta[col + 1];
                v0 = sigmoidf_acc(v0 + bb0);
                v1 = sigmoidf_acc(v1 + bb1);
                v2 = sigmoidf_acc(v2 + bb0);
                v3 = sigmoidf_acc(v3 + bb1);
            }
            float2* p0 = (float2*)&C[(size_t)r0 * HN + col];
            float2* p1 = (float2*)&C[(size_t)(r0 + 8) * HN + col];
            *p0 = make_float2(v0, v1);
            *p1 = make_float2(v2, v3);
        }
    }
}

// ---------------------------------------------------------------------------
// Fast device math
// ---------------------------------------------------------------------------
__device__ __forceinline__ float fast_ex2(float v) {
    float r;  asm("ex2.approx.f32 %0, %1;" : "=f"(r) : "f"(v));  return r;
}
__device__ __forceinline__ float fast_rcp(float v) {
    float r;  asm("rcp.approx.f32 %0, %1;" : "=f"(r) : "f"(v));  return r;
}
__device__ __forceinline__ float fast_rsqrt(float v) {
    float r;  asm("rsqrt.approx.f32 %0, %1;" : "=f"(r) : "f"(v));  return r;
}
__device__ __forceinline__ float fast_tanh(float x) {   // single MUFU.TANH
    float r;  asm("tanh.approx.f32 %0, %1;" : "=f"(r) : "f"(x));  return r;
}
__device__ __forceinline__ float fast_sigmoid(float x) {
    return fast_rcp(1.f + fast_ex2(x * -1.4426950408889634f));
}

// ---------------------------------------------------------------------------
// normalize_k: k <- k / ||k|| per (row, head). One block per row (16384),
// 256 threads; warp w handles head w, lane holds float2.
// ---------------------------------------------------------------------------
__global__ __launch_bounds__(256, 8) void normalize_k()
{
    float* pk = g_proj;   // slab 0
    const int rowi = blockIdx.x;
    const int wid  = threadIdx.x >> 5;     // head
    const int lane = threadIdx.x & 31;

    float2* p = (float2*)(pk + (size_t)rowi * HN + wid * NDIM + lane * 2);
    float2 kk = *p;
    float ss = kk.x * kk.x + kk.y * kk.y;
#pragma unroll
    for (int o = 16; o > 0; o >>= 1)
        ss += __shfl_xor_sync(0xffffffffu, ss, o);
    const float inv = fast_rsqrt(ss + 1e-12f);
    kk.x *= inv;  kk.y *= inv;
    *p = kk;
}

// ---------------------------------------------------------------------------
// Barrier-free scan, 4 elements/thread for occupancy. CTA = 128 threads = 8
// rows of one (b,h); grid = 1024 CTAs (bh = blk>>3, rowblock = blk&7).
// Thread: row = rb*8 + 2*warp + (lane>>4); owns cols jb=(lane&15)*4..+3.
// Reduces are 16-lane (4 shfl). ~55 regs -> 7-8 CTAs/SM -> 6-7 warps/SMSP.
// k pre-normalized (no norm work in the loop). Prefetch distance 1.
// ---------------------------------------------------------------------------
__global__ __launch_bounds__(128, 8) void scan_kernel(
    const float* __restrict__ S0,
    float* __restrict__ out,
    float* __restrict__ Sfin)
{
    const int blk  = blockIdx.x;
    const int bh   = blk >> 3;
    const int rb   = blk & 7;
    const int b    = bh >> 3;
    const int h    = bh & 7;
    const int tid  = threadIdx.x;
    const int w    = tid >> 5;
    const int lane = tid & 31;
    const int row  = rb * 8 + w * 2 + (lane >> 4);   // 0..63
    const int jb   = (lane & 15) * 4;                // col base

    float S[4];
    const float* S0p = S0 + (size_t)bh * NDIM * NDIM + row * NDIM + jb;
#pragma unroll
    for (int e = 0; e < 4; ++e) S[e] = S0p[e];

    const size_t slab = (size_t)ROWS * HN;
    const size_t step = (size_t)BATCH * HN;
    const float* pk = g_proj + 0 * slab + (size_t)b * HN + h * NDIM;   // normalized
    const float* pv = g_proj + 1 * slab + (size_t)b * HN + h * NDIM;
    const float* pq = g_proj + 2 * slab + (size_t)b * HN + h * NDIM;
    const float* pb = g_proj + 3 * slab + (size_t)b * HN + h * NDIM;

    float4 kc = *(const float4*)(pk + jb);
    float4 qc = *(const float4*)(pq + jb);
    float  vc = pv[row];
    float  bc = pb[row];

    float* outp = out + (size_t)b * HN + h * NDIM + row;

    for (int t = 0; t < T_STEPS; ++t) {
        float4 kp, qp;
        float  vp = 0.f, bp = 0.f;
        if (t + 1 < T_STEPS) {
            const size_t o = (size_t)(t + 1) * step;
            kp = *(const float4*)(pk + o + jb);
            qp = *(const float4*)(pq + o + jb);
            vp = __ldg(pv + o + row);
            bp = __ldg(pb + o + row);
        } else {
            kp = kc; qp = qc;
        }

        const float kv[4] = {kc.x, kc.y, kc.z, kc.w};

        // rr = S_row . k_norm  (16-lane reduce)
        float r0 = fmaf(S[0], kv[0], 0.f);
        float r1 = fmaf(S[1], kv[1], 0.f);
        r0 = fmaf(S[2], kv[2], r0);
        r1 = fmaf(S[3], kv[3], r1);
        float rr = r0 + r1;
        rr += __shfl_xor_sync(0xffffffffu, rr, 1);
        rr += __shfl_xor_sync(0xffffffffu, rr, 2);
        rr += __shfl_xor_sync(0xffffffffu, rr, 4);
        rr += __shfl_xor_sync(0xffffffffu, rr, 8);

        const float delta = vc - rr;      // k unit-norm
        const float beta  = bc;

        const float qv[4] = {qc.x, qc.y, qc.z, qc.w};

        float acc = 0.f;
#pragma unroll
        for (int e = 0; e < 4; ++e) {
            float s = fast_tanh(fmaf(delta, kv[e], beta * S[e]));
            S[e] = s;
            acc = fmaf(s, qv[e], acc);
        }
        acc += __shfl_xor_sync(0xffffffffu, acc, 1);
        acc += __shfl_xor_sync(0xffffffffu, acc, 2);
        acc += __shfl_xor_sync(0xffffffffu, acc, 4);
        acc += __shfl_xor_sync(0xffffffffu, acc, 8);

        if ((lane & 15) == 0) {
            outp[(size_t)t * step] = acc * acc * fast_sigmoid(acc);
        }

        kc = kp; qc = qp; vc = vp; bc = bp;
    }

    if (Sfin != nullptr) {
        float* sp = Sfin + (size_t)bh * NDIM * NDIM + row * NDIM + jb;
#pragma unroll
        for (int e = 0; e < 4; ++e) sp[e] = S[e];
    }
}

// ---------------------------------------------------------------------------
// Inputs: x, S0, W_k, W_v, W_q, W_beta, b_beta
// ---------------------------------------------------------------------------
extern "C" void kernel_launch(void* const* d_in, const int* in_sizes, int n_in,
                              void* d_out, int out_size)
{
    const float* x   = (const float*)d_in[0];
    const float* S0  = (const float*)d_in[1];
    const float* Wk  = (const float*)d_in[2];
    const float* Wv  = (const float*)d_in[3];
    const float* Wq  = (const float*)d_in[4];
    const float* Wb  = (const float*)d_in[5];
    const float* bbt = (const float*)d_in[6];
    float* out = (float*)d_out;

    dim3 gg(HN / GBN, ROWS / GBM, 4);
    proj_gemm_bf16<<<gg, 256>>>(x, Wk, Wv, Wq, Wb, bbt);

    normalize_k<<<ROWS, 256>>>();

    float* sfin = nullptr;
    if ((size_t)out_size >= OUT_MAIN + SFIN_ELEMS) sfin = out + OUT_MAIN;

    scan_kernel<<<BATCH * HEADS * 8, 128>>>(S0, out, sfin);
}